// round 13
// baseline (speedup 1.0000x reference)
#include <cuda_runtime.h>
#include <cuda_bf16.h>
#include <cstdint>

#define BATCH   4
#define SEQ     2048
#define DMODEL  1024
#define NHEADS  16
#define HDIM    64
#define BHEADS  (BATCH * NHEADS)        // 64
#define ROWS    (BATCH * SEQ)           // 8192

// ---------------------------------------------------------------------------
// Device-global scratch (bf16 hi/lo planes)
// ---------------------------------------------------------------------------
__device__ __nv_bfloat16 g_xh[(size_t)ROWS * DMODEL];
__device__ __nv_bfloat16 g_xl[(size_t)ROWS * DMODEL];
__device__ __nv_bfloat16 g_wh[4u * DMODEL * DMODEL];   // q,k,v,o  (n x k row-major)
__device__ __nv_bfloat16 g_wl[4u * DMODEL * DMODEL];
__device__ __nv_bfloat16 g_qkvh[3u * BHEADS * SEQ * HDIM];  // [which][bh][s][e]
__device__ __nv_bfloat16 g_qkvl[3u * BHEADS * SEQ * HDIM];
__device__ __nv_bfloat16 g_ctxh[(size_t)ROWS * DMODEL];
__device__ __nv_bfloat16 g_ctxl[(size_t)ROWS * DMODEL];

// ---------------------------------------------------------------------------
// Helpers
// ---------------------------------------------------------------------------
__device__ __forceinline__ void mma_bf16(float* c,
                                         uint32_t a0, uint32_t a1, uint32_t a2, uint32_t a3,
                                         uint32_t b0, uint32_t b1) {
    asm volatile(
        "mma.sync.aligned.m16n8k16.row.col.f32.bf16.bf16.f32 "
        "{%0,%1,%2,%3}, {%4,%5,%6,%7}, {%8,%9}, {%0,%1,%2,%3};\n"
        : "+f"(c[0]), "+f"(c[1]), "+f"(c[2]), "+f"(c[3])
        : "r"(a0), "r"(a1), "r"(a2), "r"(a3), "r"(b0), "r"(b1));
}

__device__ __forceinline__ void ldsm4(uint32_t* r, uint32_t addr) {
    asm volatile("ldmatrix.sync.aligned.m8n8.x4.shared.b16 {%0,%1,%2,%3}, [%4];"
                 : "=r"(r[0]), "=r"(r[1]), "=r"(r[2]), "=r"(r[3]) : "r"(addr));
}
__device__ __forceinline__ void ldsm4t(uint32_t* r, uint32_t addr) {
    asm volatile("ldmatrix.sync.aligned.m8n8.x4.trans.shared.b16 {%0,%1,%2,%3}, [%4];"
                 : "=r"(r[0]), "=r"(r[1]), "=r"(r[2]), "=r"(r[3]) : "r"(addr));
}

__device__ __forceinline__ void cp16(uint32_t smem_dst, const void* gmem_src) {
    asm volatile("cp.async.cg.shared.global [%0], [%1], 16;\n"
                 :: "r"(smem_dst), "l"(gmem_src));
}
__device__ __forceinline__ void cp_commit() {
    asm volatile("cp.async.commit_group;\n");
}
template <int N>
__device__ __forceinline__ void cp_wait() {
    asm volatile("cp.async.wait_group %0;\n" :: "n"(N));
}

__device__ __forceinline__ void split_bf(float x, __nv_bfloat16& h, __nv_bfloat16& l) {
    h = __float2bfloat16(x);
    l = __float2bfloat16(x - __bfloat162float(h));
}
__device__ __forceinline__ uint32_t pack2(__nv_bfloat16 a, __nv_bfloat16 b) {
    return (uint32_t)__bfloat16_as_ushort(a) | ((uint32_t)__bfloat16_as_ushort(b) << 16);
}
__device__ __forceinline__ float exp2a(float x) {
    float r;
    asm("ex2.approx.ftz.f32 %0, %1;" : "=f"(r) : "f"(x));
    return r;
}

// ---------------------------------------------------------------------------
// Pre-split kernels
// ---------------------------------------------------------------------------
__global__ void split_kernel(const float* __restrict__ src,
                             __nv_bfloat16* __restrict__ hi,
                             __nv_bfloat16* __restrict__ lo, int n)
{
    int i = (blockIdx.x * blockDim.x + threadIdx.x) * 4;
    if (i >= n) return;
    float4 v = *(const float4*)(src + i);
    __nv_bfloat16 h0, l0, h1, l1, h2, l2, h3, l3;
    split_bf(v.x, h0, l0); split_bf(v.y, h1, l1);
    split_bf(v.z, h2, l2); split_bf(v.w, h3, l3);
    *(uint32_t*)(hi + i)     = pack2(h0, h1);
    *(uint32_t*)(hi + i + 2) = pack2(h2, h3);
    *(uint32_t*)(lo + i)     = pack2(l0, l1);
    *(uint32_t*)(lo + i + 2) = pack2(l2, l3);
}

__global__ void split4_kernel(const float* __restrict__ W0, const float* __restrict__ W1,
                              const float* __restrict__ W2, const float* __restrict__ W3)
{
    const int z = blockIdx.y;
    const float* src = (z == 0) ? W0 : (z == 1) ? W1 : (z == 2) ? W2 : W3;
    const size_t nw = (size_t)DMODEL * DMODEL;
    __nv_bfloat16* hi = g_wh + z * nw;
    __nv_bfloat16* lo = g_wl + z * nw;
    int i = (blockIdx.x * blockDim.x + threadIdx.x) * 4;
    if (i >= (int)nw) return;
    float4 v = *(const float4*)(src + i);
    __nv_bfloat16 h0, l0, h1, l1, h2, l2, h3, l3;
    split_bf(v.x, h0, l0); split_bf(v.y, h1, l1);
    split_bf(v.z, h2, l2); split_bf(v.w, h3, l3);
    *(uint32_t*)(hi + i)     = pack2(h0, h1);
    *(uint32_t*)(hi + i + 2) = pack2(h2, h3);
    *(uint32_t*)(lo + i)     = pack2(l0, l1);
    *(uint32_t*)(lo + i + 2) = pack2(l2, l3);
}

// ---------------------------------------------------------------------------
// bf16x3 GEMM: 256x128 CTA tile, 512 threads (16 warps), warp tile 64x32.
// BK=32, double-buffered cp.async, single sync per k-chunk, ldmatrix frags.
// LSU-balance: 3072 cp16/kt vs 1536 HMMA/kt per SM.
// ---------------------------------------------------------------------------
#define SWG     20                    // words per row (16 data + 4 pad)
#define AROWS   256
#define BROWS   128
#define APLANE  (AROWS * SWG)         // 5120 words
#define BPLANE  (BROWS * SWG)         // 2560 words
#define BUFW    (2 * APLANE + 2 * BPLANE)   // 15360 words = 61440 B
#define GSMEM_W (2 * BUFW)            // 122880 B
#define NCP     6                     // cp16 per thread per kt (3072/512)

template <int MODE>
__global__ __launch_bounds__(512, 1)
void gemm_bf(float* __restrict__ Cout)
{
    extern __shared__ uint32_t smw[];

    const __nv_bfloat16 *Ah, *Al, *Bh, *Bl;
    if (MODE == 1) {
        Ah = g_xh;  Al = g_xl;
        const size_t wo = (size_t)blockIdx.z * DMODEL * DMODEL;
        Bh = g_wh + wo;  Bl = g_wl + wo;
    } else {
        Ah = g_ctxh;  Al = g_ctxl;
        Bh = g_wh + 3u * DMODEL * DMODEL;  Bl = g_wl + 3u * DMODEL * DMODEL;
    }

    const int tid  = threadIdx.x;
    const int lane = tid & 31;
    const int wid  = tid >> 5;
    const int wm   = wid >> 2;          // 0..3 -> m offset wm*64
    const int wn   = wid & 3;           // 0..3 -> n offset wn*32
    const int gID  = lane >> 2;
    const int tg   = lane & 3;

    const int l7   = lane & 7;
    const int l15  = lane & 15;
    const int lb8  = (lane >> 3) & 1;
    const int lb16 = (lane >> 4) & 1;

    const int brow = blockIdx.y * 256;
    const int bcol = blockIdx.x * 128;

    const uint32_t smem0 = (uint32_t)__cvta_generic_to_shared(smw);

    // Precompute per-thread staging slots: 3072 chunks = 768 rows x 4 chunks.
    // chunk c = tid*6 + i. row = c>>2 (0..767), ch = c&3.
    uint32_t sdst[NCP];                 // byte offset within buffer
    const __nv_bfloat16* gsrc[NCP];     // gmem base (k0 added per kt)
#pragma unroll
    for (int i = 0; i < NCP; i++) {
        const int c   = tid * NCP + i;
        const int row = c >> 2;
        const int ch  = c & 3;
        int p, r;
        if (row < 256)      { p = 0; r = row; }
        else if (row < 512) { p = 1; r = row - 256; }
        else if (row < 640) { p = 2; r = row - 512; }
        else                { p = 3; r = row - 640; }
        const uint32_t poff = (p == 0) ? 0u
                            : (p == 1) ? (uint32_t)APLANE
                            : (p == 2) ? (uint32_t)(2 * APLANE)
                                       : (uint32_t)(2 * APLANE + BPLANE);
        sdst[i] = (poff + (uint32_t)(r * SWG + ch * 4)) * 4u;
        const __nv_bfloat16* base =
            (p == 0) ? Ah + (size_t)(brow + r) * DMODEL :
            (p == 1) ? Al + (size_t)(brow + r) * DMODEL :
            (p == 2) ? Bh + (size_t)(bcol + r) * DMODEL :
                       Bl + (size_t)(bcol + r) * DMODEL;
        gsrc[i] = base + ch * 8;
    }

    auto stage = [&](int buf, int k0) {
        const uint32_t bb = smem0 + (uint32_t)(buf * BUFW) * 4u;
#pragma unroll
        for (int i = 0; i < NCP; i++)
            cp16(bb + sdst[i], gsrc[i] + k0);
        cp_commit();
    };

    float acc[4][4][4];
#pragma unroll
    for (int mt = 0; mt < 4; mt++)
#pragma unroll
        for (int nt = 0; nt < 4; nt++)
#pragma unroll
            for (int i = 0; i < 4; i++) acc[mt][nt][i] = 0.0f;

    stage(0, 0);

    for (int kt = 0; kt < DMODEL / 32; kt++) {
        cp_wait<0>();          // tile kt resident
        __syncthreads();       // publish; everyone done with other buffer

        if (kt + 1 < DMODEL / 32)
            stage((kt + 1) & 1, (kt + 1) * 32);   // overlaps compute

        const uint32_t bb   = smem0 + (uint32_t)((kt & 1) * BUFW) * 4u;
        const uint32_t Ah_b = bb;
        const uint32_t Al_b = bb + (uint32_t)APLANE * 4u;
        const uint32_t Bh_b = bb + (uint32_t)(2 * APLANE) * 4u;
        const uint32_t Bl_b = bb + (uint32_t)(2 * APLANE + BPLANE) * 4u;

#pragma unroll
        for (int ks = 0; ks < 2; ks++) {
            const int wb = ks * 8;

            // A fragments: 4 m16 tiles x 2 planes
            uint32_t ah[4][4], al[4][4];
#pragma unroll
            for (int mt = 0; mt < 4; mt++) {
                const uint32_t aoff =
                    (uint32_t)((wm * 64 + mt * 16 + l15) * SWG + wb + 4 * lb16) * 4u;
                ldsm4(ah[mt], Ah_b + aoff);
                ldsm4(al[mt], Al_b + aoff);
            }

            // B fragments: 2 n16 groups x 2 planes
#pragma unroll
            for (int np = 0; np < 2; np++) {
                uint32_t bhf[4], blf[4];
                const uint32_t boff =
                    (uint32_t)((wn * 32 + np * 16 + l7 + lb16 * 8) * SWG + wb + 4 * lb8) * 4u;
                ldsm4(bhf, Bh_b + boff);
                ldsm4(blf, Bl_b + boff);
#pragma unroll
                for (int half = 0; half < 2; half++) {
                    const int nt = 2 * np + half;
                    const uint32_t bh0 = bhf[2 * half], bh1 = bhf[2 * half + 1];
                    const uint32_t bl0 = blf[2 * half], bl1 = blf[2 * half + 1];
#pragma unroll
                    for (int mt = 0; mt < 4; mt++)
                        mma_bf16(acc[mt][nt], ah[mt][0], ah[mt][1], ah[mt][2], ah[mt][3], bh0, bh1);
#pragma unroll
                    for (int mt = 0; mt < 4; mt++)
                        mma_bf16(acc[mt][nt], ah[mt][0], ah[mt][1], ah[mt][2], ah[mt][3], bl0, bl1);
#pragma unroll
                    for (int mt = 0; mt < 4; mt++)
                        mma_bf16(acc[mt][nt], al[mt][0], al[mt][1], al[mt][2], al[mt][3], bh0, bh1);
                }
            }
        }
    }

    // ---- Epilogue ----
    if (MODE == 1) {
        const size_t zo = (size_t)blockIdx.z * (BHEADS * SEQ * HDIM);
#pragma unroll
        for (int mt = 0; mt < 4; mt++) {
            const int rbase = brow + wm * 64 + mt * 16 + gID;
#pragma unroll
            for (int nt = 0; nt < 4; nt++) {
                const int col = bcol + wn * 32 + nt * 8 + tg * 2;
                const int h = col >> 6;
                const int e = col & 63;
#pragma unroll
                for (int half = 0; half < 2; half++) {
                    const int r = rbase + half * 8;
                    const int b = r >> 11;
                    const int s = r & (SEQ - 1);
                    const size_t o = zo + ((size_t)(b * NHEADS + h) * SEQ + s) * HDIM + e;
                    __nv_bfloat16 h0, l0, h1, l1;
                    split_bf(acc[mt][nt][half * 2 + 0], h0, l0);
                    split_bf(acc[mt][nt][half * 2 + 1], h1, l1);
                    *(uint32_t*)(g_qkvh + o) = pack2(h0, h1);
                    *(uint32_t*)(g_qkvl + o) = pack2(l0, l1);
                }
            }
        }
    } else {
#pragma unroll
        for (int mt = 0; mt < 4; mt++) {
            const int rbase = brow + wm * 64 + mt * 16 + gID;
#pragma unroll
            for (int nt = 0; nt < 4; nt++) {
                const int col = bcol + wn * 32 + nt * 8 + tg * 2;
#pragma unroll
                for (int half = 0; half < 2; half++) {
                    const int r = rbase + half * 8;
                    float2 v = make_float2(acc[mt][nt][half * 2], acc[mt][nt][half * 2 + 1]);
                    *(float2*)(Cout + (size_t)r * DMODEL + col) = v;
                }
            }
        }
    }
}

// ---------------------------------------------------------------------------
// bf16x3 flash attention (causal) — unchanged from R12 (passing, 392 us).
// ---------------------------------------------------------------------------
#define BQ   128
#define BKT  64
#define SWF  36
#define QW   (BQ * SWF)
#define KW   (BKT * SWF)
#define KVBUF_B (4u * KW * 4u)
#define FSMEM_W (2*QW + 8*KW)        // 110592 B

__global__ __launch_bounds__(256, 2)
void flash_bf()
{
    extern __shared__ uint32_t smw[];

    const int tid  = threadIdx.x;
    const int lane = tid & 31;
    const int wid  = tid >> 5;
    const int gID  = lane >> 2;
    const int tg   = lane & 3;

    const int bh    = blockIdx.y;
    const int b     = bh >> 4;
    const int h     = bh & 15;
    const int qi    = (int)gridDim.x - 1 - (int)blockIdx.x;
    const int qbase = qi * BQ;

    const __nv_bfloat16* Qhp = g_qkvh + (size_t)bh * (SEQ * HDIM);
    const __nv_bfloat16* Qlp = g_qkvl + (size_t)bh * (SEQ * HDIM);
    const __nv_bfloat16* Khp = g_qkvh + (size_t)(BHEADS + bh) * (SEQ * HDIM);
    const __nv_bfloat16* Klp = g_qkvl + (size_t)(BHEADS + bh) * (SEQ * HDIM);
    const __nv_bfloat16* Vhp = g_qkvh + (size_t)(2 * BHEADS + bh) * (SEQ * HDIM);
    const __nv_bfloat16* Vlp = g_qkvl + (size_t)(2 * BHEADS + bh) * (SEQ * HDIM);

    const uint32_t smem0 = (uint32_t)__cvta_generic_to_shared(smw);
    const uint32_t Qh_b = smem0;
    const uint32_t Ql_b = Qh_b + QW * 4u;
    const uint32_t KV0  = Ql_b + QW * 4u;

    // ---- Q staging (once) ----
    {
        const int r  = tid >> 1;
        const int c0 = (tid & 1) * 4;
        const __nv_bfloat16* sh = Qhp + (size_t)(qbase + r) * HDIM;
        const __nv_bfloat16* sl = Qlp + (size_t)(qbase + r) * HDIM;
#pragma unroll
        for (int j = 0; j < 4; j++) {
            const int c = c0 + j;
            cp16(Qh_b + (uint32_t)(r * SWF + c * 4) * 4u, sh + c * 8);
            cp16(Ql_b + (uint32_t)(r * SWF + c * 4) * 4u, sl + c * 8);
        }
        cp_commit();
    }

    const int sr  = tid >> 2;
    const int sc0 = (tid & 3) * 2;

    auto stage_kv = [&](int buf, int kt) {
        const uint32_t bb = KV0 + (uint32_t)buf * KVBUF_B;
        const __nv_bfloat16* skh = Khp + (size_t)(kt * BKT + sr) * HDIM;
        const __nv_bfloat16* skl = Klp + (size_t)(kt * BKT + sr) * HDIM;
        const __nv_bfloat16* svh = Vhp + (size_t)(kt * BKT + sr) * HDIM;
        const __nv_bfloat16* svl = Vlp + (size_t)(kt * BKT + sr) * HDIM;
#pragma unroll
        for (int j = 0; j < 2; j++) {
            const int c = sc0 + j;
            const uint32_t so = (uint32_t)(sr * SWF + c * 4) * 4u;
            cp16(bb + so,                skh + c * 8);
            cp16(bb + KW * 4u + so,      skl + c * 8);
            cp16(bb + 2u * KW * 4u + so, svh + c * 8);
            cp16(bb + 3u * KW * 4u + so, svl + c * 8);
        }
        cp_commit();
    };

    const int l7  = lane & 7;
    const int l15 = lane & 15;
    const int lb8 = (lane >> 3) & 1;
    const int lb16 = (lane >> 4) & 1;

    const int rloc = wid * 16 + gID;

    float m0 = -1e30f, m1 = -1e30f, l0 = 0.0f, l1 = 0.0f;
    float oacc[8][4];
#pragma unroll
    for (int nt = 0; nt < 8; nt++)
#pragma unroll
        for (int i = 0; i < 4; i++) oacc[nt][i] = 0.0f;

    const int nkt = 2 * qi + 2;
    const float scale2 = 0.125f * 1.44269504f;   // 1/sqrt(64) * log2(e)

    stage_kv(0, 0);

    for (int kt = 0; kt < nkt; kt++) {
        cp_wait<0>();
        __syncthreads();

        if (kt + 1 < nkt)
            stage_kv((kt + 1) & 1, kt + 1);

        const uint32_t bb  = KV0 + (uint32_t)(kt & 1) * KVBUF_B;
        const uint32_t Kh_b = bb;
        const uint32_t Kl_b = bb + KW * 4u;
        const uint32_t Vh_b = bb + 2u * KW * 4u;
        const uint32_t Vl_b = bb + 3u * KW * 4u;

        // ---- S = Q K^T ----
        float sacc[8][4];
#pragma unroll
        for (int nt = 0; nt < 8; nt++)
#pragma unroll
            for (int i = 0; i < 4; i++) sacc[nt][i] = 0.0f;

#pragma unroll
        for (int ks = 0; ks < 4; ks++) {
            uint32_t qh[4], ql[4];
            const uint32_t qoff = (uint32_t)((rloc - gID + l15) * SWF + 8 * ks + 4 * lb16) * 4u;
            ldsm4(qh, Qh_b + qoff);
            ldsm4(ql, Ql_b + qoff);
#pragma unroll
            for (int np = 0; np < 4; np++) {
                uint32_t kh[4], kl[4];
                const uint32_t koff =
                    (uint32_t)((np * 16 + l7 + lb16 * 8) * SWF + 8 * ks + 4 * lb8) * 4u;
                ldsm4(kh, Kh_b + koff);
                ldsm4(kl, Kl_b + koff);
                mma_bf16(sacc[2 * np],     qh[0], qh[1], qh[2], qh[3], kh[0], kh[1]);
                mma_bf16(sacc[2 * np + 1], qh[0], qh[1], qh[2], qh[3], kh[2], kh[3]);
                mma_bf16(sacc[2 * np],     qh[0], qh[1], qh[2], qh[3], kl[0], kl[1]);
                mma_bf16(sacc[2 * np + 1], qh[0], qh[1], qh[2], qh[3], kl[2], kl[3]);
                mma_bf16(sacc[2 * np],     ql[0], ql[1], ql[2], ql[3], kh[0], kh[1]);
                mma_bf16(sacc[2 * np + 1], ql[0], ql[1], ql[2], ql[3], kh[2], kh[3]);
            }
        }

        // ---- Online softmax (base-2); P A-fragments in registers ----
        const bool diag = (kt >= 2 * qi);
        uint32_t pfh[4][4], pfl[4][4];

#pragma unroll
        for (int half = 0; half < 2; half++) {
            const int rg = qbase + rloc + half * 8;
            float& m = half ? m1 : m0;
            float& l = half ? l1 : l0;

            float mx = -1e30f;
#pragma unroll
            for (int nt = 0; nt < 8; nt++) {
#pragma unroll
                for (int j = 0; j < 2; j++) {
                    float s = sacc[nt][half * 2 + j] * scale2;
                    if (diag) {
                        const int cg = kt * BKT + nt * 8 + tg * 2 + j;
                        if (cg > rg) s = -1e30f;
                    }
                    sacc[nt][half * 2 + j] = s;
                    mx = fmaxf(mx, s);
                }
            }
            mx = fmaxf(mx, __shfl_xor_sync(0xffffffffu, mx, 1));
            mx = fmaxf(mx, __shfl_xor_sync(0xffffffffu, mx, 2));

            const float mn = fmaxf(m, mx);
            const float alpha = exp2a(m - mn);
            float rs = 0.0f;
#pragma unroll
            for (int nt = 0; nt < 8; nt++) {
                float p0 = exp2a(sacc[nt][half * 2 + 0] - mn);
                float p1 = exp2a(sacc[nt][half * 2 + 1] - mn);
                rs += p0 + p1;
                __nv_bfloat16 h0, lo0, h1, lo1;
                split_bf(p0, h0, lo0);
                split_bf(p1, h1, lo1);
                const int ks   = nt >> 1;
                const int slot = (nt & 1) * 2 + half;
                pfh[ks][slot] = pack2(h0, h1);
                pfl[ks][slot] = pack2(lo0, lo1);
            }
            rs += __shfl_xor_sync(0xffffffffu, rs, 1);
            rs += __shfl_xor_sync(0xffffffffu, rs, 2);
            l = l * alpha + rs;
            m = mn;
#pragma unroll
            for (int nt = 0; nt < 8; nt++) {
                oacc[nt][half * 2 + 0] *= alpha;
                oacc[nt][half * 2 + 1] *= alpha;
            }
        }

        // ---- O += P V ----
#pragma unroll
        for (int ks = 0; ks < 4; ks++) {
#pragma unroll
            for (int np = 0; np < 4; np++) {
                uint32_t vh[4], vl[4];
                const uint32_t voff =
                    (uint32_t)((ks * 16 + l7 + lb8 * 8) * SWF + 8 * np + 4 * lb16) * 4u;
                ldsm4t(vh, Vh_b + voff);
                ldsm4t(vl, Vl_b + voff);
                mma_bf16(oacc[2 * np],     pfh[ks][0], pfh[ks][1], pfh[ks][2], pfh[ks][3], vh[0], vh[1]);
                mma_bf16(oacc[2 * np + 1], pfh[ks][0], pfh[ks][1], pfh[ks][2], pfh[ks][3], vh[2], vh[3]);
                mma_bf16(oacc[2 * np],     pfh[ks][0], pfh[ks][1], pfh[ks][2], pfh[ks][3], vl[0], vl[1]);
                mma_bf16(oacc[2 * np + 1], pfh[ks][0], pfh[ks][1], pfh[ks][2], pfh[ks][3], vl[2], vl[3]);
                mma_bf16(oacc[2 * np],     pfl[ks][0], pfl[ks][1], pfl[ks][2], pfl[ks][3], vh[0], vh[1]);
                mma_bf16(oacc[2 * np + 1], pfl[ks][0], pfl[ks][1], pfl[ks][2], pfl[ks][3], vh[2], vh[3]);
            }
        }
    }

    // ---- Epilogue ----
    const float inv0 = 1.0f / l0;
    const float inv1 = 1.0f / l1;
#pragma unroll
    for (int half = 0; half < 2; half++) {
        const float inv = half ? inv1 : inv0;
        const int rg = qbase + rloc + half * 8;
        const size_t rowo = ((size_t)b * SEQ + rg) * DMODEL + h * HDIM;
#pragma unroll
        for (int nt = 0; nt < 8; nt++) {
            float v0 = oacc[nt][half * 2 + 0] * inv;
            float v1 = oacc[nt][half * 2 + 1] * inv;
            __nv_bfloat16 h0, lo0, h1, lo1;
            split_bf(v0, h0, lo0);
            split_bf(v1, h1, lo1);
            const size_t o = rowo + nt * 8 + tg * 2;
            *(uint32_t*)(g_ctxh + o) = pack2(h0, h1);
            *(uint32_t*)(g_ctxl + o) = pack2(lo0, lo1);
        }
    }
}

// ---------------------------------------------------------------------------
extern "C" void kernel_launch(void* const* d_in, const int* in_sizes, int n_in,
                              void* d_out, int out_size)
{
    const float* x  = (const float*)d_in[0];
    const float* Wq = (const float*)d_in[1];
    const float* Wk = (const float*)d_in[2];
    const float* Wv = (const float*)d_in[3];
    const float* Wo = (const float*)d_in[4];
    float* out = (float*)d_out;

    const int gsmem = GSMEM_W * 4;     // 122880 B
    const int fsmem = FSMEM_W * 4;     // 110592 B

    cudaFuncSetAttribute(gemm_bf<1>,
                         cudaFuncAttributeMaxDynamicSharedMemorySize, gsmem);
    cudaFuncSetAttribute(gemm_bf<0>,
                         cudaFuncAttributeMaxDynamicSharedMemorySize, gsmem);
    cudaFuncSetAttribute(flash_bf,
                         cudaFuncAttributeMaxDynamicSharedMemorySize, fsmem);

    __nv_bfloat16 *xh, *xl;
    cudaGetSymbolAddress((void**)&xh, g_xh);
    cudaGetSymbolAddress((void**)&xl, g_xl);

    const int nx = ROWS * DMODEL;
    const int nw = DMODEL * DMODEL;
    split_kernel<<<(nx / 4 + 255) / 256, 256>>>(x, xh, xl, nx);
    dim3 gs((nw / 4 + 255) / 256, 4);
    split4_kernel<<<gs, 256>>>(Wq, Wk, Wv, Wo);

    // 1) QKV projections (256x128 tiles)
    dim3 g1(DMODEL / 128, ROWS / 256, 3);
    gemm_bf<1><<<g1, 512, gsmem>>>(nullptr);

    // 2) Causal flash attention
    dim3 g2(SEQ / BQ, BHEADS);
    flash_bf<<<g2, 256, fsmem>>>();

    // 3) Output projection
    dim3 g3(DMODEL / 128, ROWS / 256, 1);
    gemm_bf<0><<<g3, 512, gsmem>>>(out);
}

// round 14
// speedup vs baseline: 1.3053x; 1.3053x over previous
#include <cuda_runtime.h>
#include <cuda_bf16.h>
#include <cuda_fp16.h>
#include <cstdint>

#define BATCH   4
#define SEQ     2048
#define DMODEL  1024
#define NHEADS  16
#define HDIM    64
#define BHEADS  (BATCH * NHEADS)        // 64
#define ROWS    (BATCH * SEQ)           // 8192

// ---------------------------------------------------------------------------
// Device-global scratch. Q/K regions: bf16 hi/lo planes. V region: fp16 hi/lo.
// ---------------------------------------------------------------------------
__device__ __nv_bfloat16 g_xh[(size_t)ROWS * DMODEL];
__device__ __nv_bfloat16 g_xl[(size_t)ROWS * DMODEL];
__device__ __nv_bfloat16 g_wh[4u * DMODEL * DMODEL];   // q,k,v,o  (n x k row-major)
__device__ __nv_bfloat16 g_wl[4u * DMODEL * DMODEL];
__device__ __nv_bfloat16 g_qkvh[3u * BHEADS * SEQ * HDIM];  // [which][bh][s][e]
__device__ __nv_bfloat16 g_qkvl[3u * BHEADS * SEQ * HDIM];
__device__ __nv_bfloat16 g_ctxh[(size_t)ROWS * DMODEL];
__device__ __nv_bfloat16 g_ctxl[(size_t)ROWS * DMODEL];

// ---------------------------------------------------------------------------
// Helpers
// ---------------------------------------------------------------------------
__device__ __forceinline__ void mma_bf16(float* c,
                                         uint32_t a0, uint32_t a1, uint32_t a2, uint32_t a3,
                                         uint32_t b0, uint32_t b1) {
    asm volatile(
        "mma.sync.aligned.m16n8k16.row.col.f32.bf16.bf16.f32 "
        "{%0,%1,%2,%3}, {%4,%5,%6,%7}, {%8,%9}, {%0,%1,%2,%3};\n"
        : "+f"(c[0]), "+f"(c[1]), "+f"(c[2]), "+f"(c[3])
        : "r"(a0), "r"(a1), "r"(a2), "r"(a3), "r"(b0), "r"(b1));
}
__device__ __forceinline__ void mma_f16(float* c,
                                        uint32_t a0, uint32_t a1, uint32_t a2, uint32_t a3,
                                        uint32_t b0, uint32_t b1) {
    asm volatile(
        "mma.sync.aligned.m16n8k16.row.col.f32.f16.f16.f32 "
        "{%0,%1,%2,%3}, {%4,%5,%6,%7}, {%8,%9}, {%0,%1,%2,%3};\n"
        : "+f"(c[0]), "+f"(c[1]), "+f"(c[2]), "+f"(c[3])
        : "r"(a0), "r"(a1), "r"(a2), "r"(a3), "r"(b0), "r"(b1));
}

__device__ __forceinline__ void ldsm4(uint32_t* r, uint32_t addr) {
    asm volatile("ldmatrix.sync.aligned.m8n8.x4.shared.b16 {%0,%1,%2,%3}, [%4];"
                 : "=r"(r[0]), "=r"(r[1]), "=r"(r[2]), "=r"(r[3]) : "r"(addr));
}
__device__ __forceinline__ void ldsm4t(uint32_t* r, uint32_t addr) {
    asm volatile("ldmatrix.sync.aligned.m8n8.x4.trans.shared.b16 {%0,%1,%2,%3}, [%4];"
                 : "=r"(r[0]), "=r"(r[1]), "=r"(r[2]), "=r"(r[3]) : "r"(addr));
}

__device__ __forceinline__ void cp16(uint32_t smem_dst, const void* gmem_src) {
    asm volatile("cp.async.cg.shared.global [%0], [%1], 16;\n"
                 :: "r"(smem_dst), "l"(gmem_src));
}
__device__ __forceinline__ void cp_commit() {
    asm volatile("cp.async.commit_group;\n");
}
template <int N>
__device__ __forceinline__ void cp_wait() {
    asm volatile("cp.async.wait_group %0;\n" :: "n"(N));
}

__device__ __forceinline__ void split_bf(float x, __nv_bfloat16& h, __nv_bfloat16& l) {
    h = __float2bfloat16(x);
    l = __float2bfloat16(x - __bfloat162float(h));
}
__device__ __forceinline__ uint32_t pack2(__nv_bfloat16 a, __nv_bfloat16 b) {
    return (uint32_t)__bfloat16_as_ushort(a) | ((uint32_t)__bfloat16_as_ushort(b) << 16);
}
__device__ __forceinline__ uint32_t pack2h(__half a, __half b) {
    return (uint32_t)__half_as_ushort(a) | ((uint32_t)__half_as_ushort(b) << 16);
}
__device__ __forceinline__ float exp2a(float x) {
    float r;
    asm("ex2.approx.ftz.f32 %0, %1;" : "=f"(r) : "f"(x));
    return r;
}

// ---------------------------------------------------------------------------
// Pre-split kernels
// ---------------------------------------------------------------------------
__global__ void split_kernel(const float* __restrict__ src,
                             __nv_bfloat16* __restrict__ hi,
                             __nv_bfloat16* __restrict__ lo, int n)
{
    int i = (blockIdx.x * blockDim.x + threadIdx.x) * 4;
    if (i >= n) return;
    float4 v = *(const float4*)(src + i);
    __nv_bfloat16 h0, l0, h1, l1, h2, l2, h3, l3;
    split_bf(v.x, h0, l0); split_bf(v.y, h1, l1);
    split_bf(v.z, h2, l2); split_bf(v.w, h3, l3);
    *(uint32_t*)(hi + i)     = pack2(h0, h1);
    *(uint32_t*)(hi + i + 2) = pack2(h2, h3);
    *(uint32_t*)(lo + i)     = pack2(l0, l1);
    *(uint32_t*)(lo + i + 2) = pack2(l2, l3);
}

__global__ void split4_kernel(const float* __restrict__ W0, const float* __restrict__ W1,
                              const float* __restrict__ W2, const float* __restrict__ W3)
{
    const int z = blockIdx.y;
    const float* src = (z == 0) ? W0 : (z == 1) ? W1 : (z == 2) ? W2 : W3;
    const size_t nw = (size_t)DMODEL * DMODEL;
    __nv_bfloat16* hi = g_wh + z * nw;
    __nv_bfloat16* lo = g_wl + z * nw;
    int i = (blockIdx.x * blockDim.x + threadIdx.x) * 4;
    if (i >= (int)nw) return;
    float4 v = *(const float4*)(src + i);
    __nv_bfloat16 h0, l0, h1, l1, h2, l2, h3, l3;
    split_bf(v.x, h0, l0); split_bf(v.y, h1, l1);
    split_bf(v.z, h2, l2); split_bf(v.w, h3, l3);
    *(uint32_t*)(hi + i)     = pack2(h0, h1);
    *(uint32_t*)(hi + i + 2) = pack2(h2, h3);
    *(uint32_t*)(lo + i)     = pack2(l0, l1);
    *(uint32_t*)(lo + i + 2) = pack2(l2, l3);
}

// ---------------------------------------------------------------------------
// bf16x3 GEMM (R12-proven): 128x128 CTA, 256 thr, 2 CTAs/SM, single-sync
// pipeline, ldmatrix fragments, product-major mma order.
// MODE 1, z==2 (V): epilogue splits to fp16 hi/lo (for fp16 PV in flash).
// ---------------------------------------------------------------------------
#define SWG     20
#define PLANEW  (128 * SWG)
#define GSMEM_W (2 * 4 * PLANEW)

template <int MODE>
__global__ __launch_bounds__(256, 2)
void gemm_bf(float* __restrict__ Cout)
{
    extern __shared__ uint32_t smw[];

    const __nv_bfloat16 *Ah, *Al, *Bh, *Bl;
    if (MODE == 1) {
        Ah = g_xh;  Al = g_xl;
        const size_t wo = (size_t)blockIdx.z * DMODEL * DMODEL;
        Bh = g_wh + wo;  Bl = g_wl + wo;
    } else {
        Ah = g_ctxh;  Al = g_ctxl;
        Bh = g_wh + 3u * DMODEL * DMODEL;  Bl = g_wl + 3u * DMODEL * DMODEL;
    }

    const int tid  = threadIdx.x;
    const int lane = tid & 31;
    const int wid  = tid >> 5;
    const int wm   = wid >> 1;
    const int wn   = wid & 1;
    const int gID  = lane >> 2;
    const int tg   = lane & 3;

    const int l7   = lane & 7;
    const int l15  = lane & 15;
    const int lb8  = (lane >> 3) & 1;
    const int lb16 = (lane >> 4) & 1;

    const int brow = blockIdx.y * 128;
    const int bcol = blockIdx.x * 128;

    const int srow = tid >> 1;
    const int cb   = (tid & 1) * 2;

    const uint32_t smem0 = (uint32_t)__cvta_generic_to_shared(smw);

    auto stage = [&](int buf, int k0) {
        const uint32_t base = smem0 + (uint32_t)(buf * 4 * PLANEW) * 4u;
        const __nv_bfloat16* gsrc[4] = {
            Ah + (size_t)(brow + srow) * DMODEL + k0,
            Al + (size_t)(brow + srow) * DMODEL + k0,
            Bh + (size_t)(bcol + srow) * DMODEL + k0,
            Bl + (size_t)(bcol + srow) * DMODEL + k0 };
#pragma unroll
        for (int p = 0; p < 4; p++) {
#pragma unroll
            for (int j = 0; j < 2; j++) {
                const int c = cb + j;
                cp16(base + (uint32_t)(p * PLANEW + srow * SWG + c * 4) * 4u,
                     gsrc[p] + c * 8);
            }
        }
        cp_commit();
    };

    float acc[2][8][4];
#pragma unroll
    for (int mt = 0; mt < 2; mt++)
#pragma unroll
        for (int nt = 0; nt < 8; nt++)
#pragma unroll
            for (int i = 0; i < 4; i++) acc[mt][nt][i] = 0.0f;

    stage(0, 0);

    for (int kt = 0; kt < DMODEL / 32; kt++) {
        cp_wait<0>();
        __syncthreads();

        if (kt + 1 < DMODEL / 32)
            stage((kt + 1) & 1, (kt + 1) * 32);

        const uint32_t bufw = (uint32_t)((kt & 1) * 4 * PLANEW) * 4u;
        const uint32_t Ah_b = smem0 + bufw;
        const uint32_t Al_b = Ah_b + PLANEW * 4u;
        const uint32_t Bh_b = Al_b + PLANEW * 4u;
        const uint32_t Bl_b = Bh_b + PLANEW * 4u;

#pragma unroll
        for (int ks = 0; ks < 2; ks++) {
            const int wb = ks * 8;

            uint32_t ah[2][4], al[2][4];
#pragma unroll
            for (int mt = 0; mt < 2; mt++) {
                const uint32_t aoff =
                    (uint32_t)((wm * 32 + mt * 16 + l15) * SWG + wb + 4 * lb16) * 4u;
                ldsm4(ah[mt], Ah_b + aoff);
                ldsm4(al[mt], Al_b + aoff);
            }

#pragma unroll
            for (int np = 0; np < 4; np++) {
                uint32_t bhf[4], blf[4];
                const uint32_t boff =
                    (uint32_t)((wn * 64 + np * 16 + l7 + lb16 * 8) * SWG + wb + 4 * lb8) * 4u;
                ldsm4(bhf, Bh_b + boff);
                ldsm4(blf, Bl_b + boff);
#pragma unroll
                for (int half = 0; half < 2; half++) {
                    const int nt = 2 * np + half;
#pragma unroll
                    for (int mt = 0; mt < 2; mt++)
                        mma_bf16(acc[mt][nt], ah[mt][0], ah[mt][1], ah[mt][2], ah[mt][3],
                                 bhf[2 * half], bhf[2 * half + 1]);
                }
#pragma unroll
                for (int half = 0; half < 2; half++) {
                    const int nt = 2 * np + half;
#pragma unroll
                    for (int mt = 0; mt < 2; mt++)
                        mma_bf16(acc[mt][nt], ah[mt][0], ah[mt][1], ah[mt][2], ah[mt][3],
                                 blf[2 * half], blf[2 * half + 1]);
                }
#pragma unroll
                for (int half = 0; half < 2; half++) {
                    const int nt = 2 * np + half;
#pragma unroll
                    for (int mt = 0; mt < 2; mt++)
                        mma_bf16(acc[mt][nt], al[mt][0], al[mt][1], al[mt][2], al[mt][3],
                                 bhf[2 * half], bhf[2 * half + 1]);
                }
            }
        }
    }

    if (MODE == 1) {
        const bool isV = (blockIdx.z == 2);
        const size_t zo = (size_t)blockIdx.z * (BHEADS * SEQ * HDIM);
#pragma unroll
        for (int mt = 0; mt < 2; mt++) {
            const int rbase = brow + wm * 32 + mt * 16 + gID;
#pragma unroll
            for (int nt = 0; nt < 8; nt++) {
                const int col = bcol + wn * 64 + nt * 8 + tg * 2;
                const int h = col >> 6;
                const int e = col & 63;
#pragma unroll
                for (int half = 0; half < 2; half++) {
                    const int r = rbase + half * 8;
                    const int b = r >> 11;
                    const int s = r & (SEQ - 1);
                    const size_t o = zo + ((size_t)(b * NHEADS + h) * SEQ + s) * HDIM + e;
                    const float v0 = acc[mt][nt][half * 2 + 0];
                    const float v1 = acc[mt][nt][half * 2 + 1];
                    if (isV) {
                        __half h0 = __float2half_rn(v0);
                        __half l0 = __float2half_rn(v0 - __half2float(h0));
                        __half h1 = __float2half_rn(v1);
                        __half l1 = __float2half_rn(v1 - __half2float(h1));
                        *(uint32_t*)(g_qkvh + o) = pack2h(h0, h1);
                        *(uint32_t*)(g_qkvl + o) = pack2h(l0, l1);
                    } else {
                        __nv_bfloat16 h0, l0, h1, l1;
                        split_bf(v0, h0, l0);
                        split_bf(v1, h1, l1);
                        *(uint32_t*)(g_qkvh + o) = pack2(h0, h1);
                        *(uint32_t*)(g_qkvl + o) = pack2(l0, l1);
                    }
                }
            }
        }
    } else {
#pragma unroll
        for (int mt = 0; mt < 2; mt++) {
            const int rbase = brow + wm * 32 + mt * 16 + gID;
#pragma unroll
            for (int nt = 0; nt < 8; nt++) {
                const int col = bcol + wn * 64 + nt * 8 + tg * 2;
#pragma unroll
                for (int half = 0; half < 2; half++) {
                    const int r = rbase + half * 8;
                    float2 v = make_float2(acc[mt][nt][half * 2], acc[mt][nt][half * 2 + 1]);
                    *(float2*)(Cout + (size_t)r * DMODEL + col) = v;
                }
            }
        }
    }
}

// ---------------------------------------------------------------------------
// Flash attention (causal). QK: bf16x3. PV: fp16 P (hi-only) x fp16 V (hi/lo)
// -> 2 products. Double-buffered K/V, single-sync pipeline, exp2 softmax.
// ---------------------------------------------------------------------------
#define BQ   128
#define BKT  64
#define SWF  36
#define QW   (BQ * SWF)
#define KW   (BKT * SWF)
#define KVBUF_B (4u * KW * 4u)
#define FSMEM_W (2*QW + 8*KW)        // 110592 B

__global__ __launch_bounds__(256, 2)
void flash_bf()
{
    extern __shared__ uint32_t smw[];

    const int tid  = threadIdx.x;
    const int lane = tid & 31;
    const int wid  = tid >> 5;
    const int gID  = lane >> 2;
    const int tg   = lane & 3;

    const int bh    = blockIdx.y;
    const int b     = bh >> 4;
    const int h     = bh & 15;
    const int qi    = (int)gridDim.x - 1 - (int)blockIdx.x;
    const int qbase = qi * BQ;

    const __nv_bfloat16* Qhp = g_qkvh + (size_t)bh * (SEQ * HDIM);
    const __nv_bfloat16* Qlp = g_qkvl + (size_t)bh * (SEQ * HDIM);
    const __nv_bfloat16* Khp = g_qkvh + (size_t)(BHEADS + bh) * (SEQ * HDIM);
    const __nv_bfloat16* Klp = g_qkvl + (size_t)(BHEADS + bh) * (SEQ * HDIM);
    const __nv_bfloat16* Vhp = g_qkvh + (size_t)(2 * BHEADS + bh) * (SEQ * HDIM);  // fp16 bits
    const __nv_bfloat16* Vlp = g_qkvl + (size_t)(2 * BHEADS + bh) * (SEQ * HDIM);  // fp16 bits

    const uint32_t smem0 = (uint32_t)__cvta_generic_to_shared(smw);
    const uint32_t Qh_b = smem0;
    const uint32_t Ql_b = Qh_b + QW * 4u;
    const uint32_t KV0  = Ql_b + QW * 4u;

    // ---- Q staging (once) ----
    {
        const int r  = tid >> 1;
        const int c0 = (tid & 1) * 4;
        const __nv_bfloat16* sh = Qhp + (size_t)(qbase + r) * HDIM;
        const __nv_bfloat16* sl = Qlp + (size_t)(qbase + r) * HDIM;
#pragma unroll
        for (int j = 0; j < 4; j++) {
            const int c = c0 + j;
            cp16(Qh_b + (uint32_t)(r * SWF + c * 4) * 4u, sh + c * 8);
            cp16(Ql_b + (uint32_t)(r * SWF + c * 4) * 4u, sl + c * 8);
        }
        cp_commit();
    }

    const int sr  = tid >> 2;
    const int sc0 = (tid & 3) * 2;

    auto stage_kv = [&](int buf, int kt) {
        const uint32_t bb = KV0 + (uint32_t)buf * KVBUF_B;
        const __nv_bfloat16* skh = Khp + (size_t)(kt * BKT + sr) * HDIM;
        const __nv_bfloat16* skl = Klp + (size_t)(kt * BKT + sr) * HDIM;
        const __nv_bfloat16* svh = Vhp + (size_t)(kt * BKT + sr) * HDIM;
        const __nv_bfloat16* svl = Vlp + (size_t)(kt * BKT + sr) * HDIM;
#pragma unroll
        for (int j = 0; j < 2; j++) {
            const int c = sc0 + j;
            const uint32_t so = (uint32_t)(sr * SWF + c * 4) * 4u;
            cp16(bb + so,                skh + c * 8);
            cp16(bb + KW * 4u + so,      skl + c * 8);
            cp16(bb + 2u * KW * 4u + so, svh + c * 8);
            cp16(bb + 3u * KW * 4u + so, svl + c * 8);
        }
        cp_commit();
    };

    const int l7  = lane & 7;
    const int l15 = lane & 15;
    const int lb8 = (lane >> 3) & 1;
    const int lb16 = (lane >> 4) & 1;

    const int rloc = wid * 16 + gID;

    float m0 = -1e30f, m1 = -1e30f, l0 = 0.0f, l1 = 0.0f;
    float oacc[8][4];
#pragma unroll
    for (int nt = 0; nt < 8; nt++)
#pragma unroll
        for (int i = 0; i < 4; i++) oacc[nt][i] = 0.0f;

    const int nkt = 2 * qi + 2;
    const float scale2 = 0.125f * 1.44269504f;   // 1/sqrt(64) * log2(e)

    stage_kv(0, 0);

    for (int kt = 0; kt < nkt; kt++) {
        cp_wait<0>();
        __syncthreads();

        if (kt + 1 < nkt)
            stage_kv((kt + 1) & 1, kt + 1);

        const uint32_t bb  = KV0 + (uint32_t)(kt & 1) * KVBUF_B;
        const uint32_t Kh_b = bb;
        const uint32_t Kl_b = bb + KW * 4u;
        const uint32_t Vh_b = bb + 2u * KW * 4u;
        const uint32_t Vl_b = bb + 3u * KW * 4u;

        // ---- S = Q K^T (bf16x3) ----
        float sacc[8][4];
#pragma unroll
        for (int nt = 0; nt < 8; nt++)
#pragma unroll
            for (int i = 0; i < 4; i++) sacc[nt][i] = 0.0f;

#pragma unroll
        for (int ks = 0; ks < 4; ks++) {
            uint32_t qh[4], ql[4];
            const uint32_t qoff = (uint32_t)((rloc - gID + l15) * SWF + 8 * ks + 4 * lb16) * 4u;
            ldsm4(qh, Qh_b + qoff);
            ldsm4(ql, Ql_b + qoff);
#pragma unroll
            for (int np = 0; np < 4; np++) {
                uint32_t kh[4], kl[4];
                const uint32_t koff =
                    (uint32_t)((np * 16 + l7 + lb16 * 8) * SWF + 8 * ks + 4 * lb8) * 4u;
                ldsm4(kh, Kh_b + koff);
                ldsm4(kl, Kl_b + koff);
                mma_bf16(sacc[2 * np],     qh[0], qh[1], qh[2], qh[3], kh[0], kh[1]);
                mma_bf16(sacc[2 * np + 1], qh[0], qh[1], qh[2], qh[3], kh[2], kh[3]);
                mma_bf16(sacc[2 * np],     qh[0], qh[1], qh[2], qh[3], kl[0], kl[1]);
                mma_bf16(sacc[2 * np + 1], qh[0], qh[1], qh[2], qh[3], kl[2], kl[3]);
                mma_bf16(sacc[2 * np],     ql[0], ql[1], ql[2], ql[3], kh[0], kh[1]);
                mma_bf16(sacc[2 * np + 1], ql[0], ql[1], ql[2], ql[3], kh[2], kh[3]);
            }
        }

        // ---- Online softmax (base-2); P as fp16 A-fragments ----
        const bool diag = (kt >= 2 * qi);
        uint32_t pf[4][4];

#pragma unroll
        for (int half = 0; half < 2; half++) {
            const int rg = qbase + rloc + half * 8;
            float& m = half ? m1 : m0;
            float& l = half ? l1 : l0;

            float mx = -1e30f;
#pragma unroll
            for (int nt = 0; nt < 8; nt++) {
#pragma unroll
                for (int j = 0; j < 2; j++) {
                    float s = sacc[nt][half * 2 + j] * scale2;
                    if (diag) {
                        const int cg = kt * BKT + nt * 8 + tg * 2 + j;
                        if (cg > rg) s = -1e30f;
                    }
                    sacc[nt][half * 2 + j] = s;
                    mx = fmaxf(mx, s);
                }
            }
            mx = fmaxf(mx, __shfl_xor_sync(0xffffffffu, mx, 1));
            mx = fmaxf(mx, __shfl_xor_sync(0xffffffffu, mx, 2));

            const float mn = fmaxf(m, mx);
            const float alpha = exp2a(m - mn);
            float rs = 0.0f;
#pragma unroll
            for (int nt = 0; nt < 8; nt++) {
                float p0 = exp2a(sacc[nt][half * 2 + 0] - mn);
                float p1 = exp2a(sacc[nt][half * 2 + 1] - mn);
                rs += p0 + p1;
                const int ks   = nt >> 1;
                const int slot = (nt & 1) * 2 + half;
                pf[ks][slot] = pack2h(__float2half_rn(p0), __float2half_rn(p1));
            }
            rs += __shfl_xor_sync(0xffffffffu, rs, 1);
            rs += __shfl_xor_sync(0xffffffffu, rs, 2);
            l = l * alpha + rs;
            m = mn;
#pragma unroll
            for (int nt = 0; nt < 8; nt++) {
                oacc[nt][half * 2 + 0] *= alpha;
                oacc[nt][half * 2 + 1] *= alpha;
            }
        }

        // ---- O += P V (fp16 x 2 products) ----
#pragma unroll
        for (int ks = 0; ks < 4; ks++) {
#pragma unroll
            for (int np = 0; np < 4; np++) {
                uint32_t vh[4], vl[4];
                const uint32_t voff =
                    (uint32_t)((ks * 16 + l7 + lb8 * 8) * SWF + 8 * np + 4 * lb16) * 4u;
                ldsm4t(vh, Vh_b + voff);
                ldsm4t(vl, Vl_b + voff);
                mma_f16(oacc[2 * np],     pf[ks][0], pf[ks][1], pf[ks][2], pf[ks][3], vh[0], vh[1]);
                mma_f16(oacc[2 * np + 1], pf[ks][0], pf[ks][1], pf[ks][2], pf[ks][3], vh[2], vh[3]);
                mma_f16(oacc[2 * np],     pf[ks][0], pf[ks][1], pf[ks][2], pf[ks][3], vl[0], vl[1]);
                mma_f16(oacc[2 * np + 1], pf[ks][0], pf[ks][1], pf[ks][2], pf[ks][3], vl[2], vl[3]);
            }
        }
    }

    // ---- Epilogue ----
    const float inv0 = 1.0f / l0;
    const float inv1 = 1.0f / l1;
#pragma unroll
    for (int half = 0; half < 2; half++) {
        const float inv = half ? inv1 : inv0;
        const int rg = qbase + rloc + half * 8;
        const size_t rowo = ((size_t)b * SEQ + rg) * DMODEL + h * HDIM;
#pragma unroll
        for (int nt = 0; nt < 8; nt++) {
            float v0 = oacc[nt][half * 2 + 0] * inv;
            float v1 = oacc[nt][half * 2 + 1] * inv;
            __nv_bfloat16 h0, lo0, h1, lo1;
            split_bf(v0, h0, lo0);
            split_bf(v1, h1, lo1);
            const size_t o = rowo + nt * 8 + tg * 2;
            *(uint32_t*)(g_ctxh + o) = pack2(h0, h1);
            *(uint32_t*)(g_ctxl + o) = pack2(lo0, lo1);
        }
    }
}

// ---------------------------------------------------------------------------
extern "C" void kernel_launch(void* const* d_in, const int* in_sizes, int n_in,
                              void* d_out, int out_size)
{
    const float* x  = (const float*)d_in[0];
    const float* Wq = (const float*)d_in[1];
    const float* Wk = (const float*)d_in[2];
    const float* Wv = (const float*)d_in[3];
    const float* Wo = (const float*)d_in[4];
    float* out = (float*)d_out;

    const int gsmem = GSMEM_W * 4;     // 81920 B
    const int fsmem = FSMEM_W * 4;     // 110592 B

    cudaFuncSetAttribute(gemm_bf<1>,
                         cudaFuncAttributeMaxDynamicSharedMemorySize, gsmem);
    cudaFuncSetAttribute(gemm_bf<0>,
                         cudaFuncAttributeMaxDynamicSharedMemorySize, gsmem);
    cudaFuncSetAttribute(flash_bf,
                         cudaFuncAttributeMaxDynamicSharedMemorySize, fsmem);

    __nv_bfloat16 *xh, *xl;
    cudaGetSymbolAddress((void**)&xh, g_xh);
    cudaGetSymbolAddress((void**)&xl, g_xl);

    const int nx = ROWS * DMODEL;
    const int nw = DMODEL * DMODEL;
    split_kernel<<<(nx / 4 + 255) / 256, 256>>>(x, xh, xl, nx);
    dim3 gs((nw / 4 + 255) / 256, 4);
    split4_kernel<<<gs, 256>>>(Wq, Wk, Wv, Wo);

    // 1) QKV projections
    dim3 g1(DMODEL / 128, ROWS / 128, 3);
    gemm_bf<1><<<g1, 256, gsmem>>>(nullptr);

    // 2) Causal flash attention
    dim3 g2(SEQ / BQ, BHEADS);
    flash_bf<<<g2, 256, fsmem>>>();

    // 3) Output projection
    dim3 g3(DMODEL / 128, ROWS / 128, 1);
    gemm_bf<0><<<g3, 256, gsmem>>>(out);
}

// round 16
// speedup vs baseline: 1.4374x; 1.1012x over previous
#include <cuda_runtime.h>
#include <cuda_bf16.h>
#include <cuda_fp16.h>
#include <cstdint>

#define BATCH   4
#define SEQ     2048
#define DMODEL  1024
#define NHEADS  16
#define HDIM    64
#define BHEADS  (BATCH * NHEADS)        // 64
#define ROWS    (BATCH * SEQ)           // 8192

// ---------------------------------------------------------------------------
// Device-global scratch.
//  - x: bf16 hi/lo (for Q/K proj) + fp16 hi/lo (for V proj)
//  - W: z 0,1 bf16 planes; z 2,3 fp16 planes (hi used; lo spare)
//  - qkv: Q,K bf16 planes; V fp16 planes
//  - ctx: fp16 hi/lo
// ---------------------------------------------------------------------------
__device__ __nv_bfloat16 g_xh[(size_t)ROWS * DMODEL];
__device__ __nv_bfloat16 g_xl[(size_t)ROWS * DMODEL];
__device__ __half        g_x16h[(size_t)ROWS * DMODEL];
__device__ __half        g_x16l[(size_t)ROWS * DMODEL];
__device__ __nv_bfloat16 g_wh[4u * DMODEL * DMODEL];
__device__ __nv_bfloat16 g_wl[4u * DMODEL * DMODEL];
__device__ __nv_bfloat16 g_qkvh[3u * BHEADS * SEQ * HDIM];
__device__ __nv_bfloat16 g_qkvl[3u * BHEADS * SEQ * HDIM];
__device__ __nv_bfloat16 g_ctxh[(size_t)ROWS * DMODEL];   // fp16 bits
__device__ __nv_bfloat16 g_ctxl[(size_t)ROWS * DMODEL];   // fp16 bits

// ---------------------------------------------------------------------------
// Helpers
// ---------------------------------------------------------------------------
__device__ __forceinline__ void mma_bf16(float* c,
                                         uint32_t a0, uint32_t a1, uint32_t a2, uint32_t a3,
                                         uint32_t b0, uint32_t b1) {
    asm volatile(
        "mma.sync.aligned.m16n8k16.row.col.f32.bf16.bf16.f32 "
        "{%0,%1,%2,%3}, {%4,%5,%6,%7}, {%8,%9}, {%0,%1,%2,%3};\n"
        : "+f"(c[0]), "+f"(c[1]), "+f"(c[2]), "+f"(c[3])
        : "r"(a0), "r"(a1), "r"(a2), "r"(a3), "r"(b0), "r"(b1));
}
__device__ __forceinline__ void mma_f16(float* c,
                                        uint32_t a0, uint32_t a1, uint32_t a2, uint32_t a3,
                                        uint32_t b0, uint32_t b1) {
    asm volatile(
        "mma.sync.aligned.m16n8k16.row.col.f32.f16.f16.f32 "
        "{%0,%1,%2,%3}, {%4,%5,%6,%7}, {%8,%9}, {%0,%1,%2,%3};\n"
        : "+f"(c[0]), "+f"(c[1]), "+f"(c[2]), "+f"(c[3])
        : "r"(a0), "r"(a1), "r"(a2), "r"(a3), "r"(b0), "r"(b1));
}

__device__ __forceinline__ void ldsm4(uint32_t* r, uint32_t addr) {
    asm volatile("ldmatrix.sync.aligned.m8n8.x4.shared.b16 {%0,%1,%2,%3}, [%4];"
                 : "=r"(r[0]), "=r"(r[1]), "=r"(r[2]), "=r"(r[3]) : "r"(addr));
}
__device__ __forceinline__ void ldsm4t(uint32_t* r, uint32_t addr) {
    asm volatile("ldmatrix.sync.aligned.m8n8.x4.trans.shared.b16 {%0,%1,%2,%3}, [%4];"
                 : "=r"(r[0]), "=r"(r[1]), "=r"(r[2]), "=r"(r[3]) : "r"(addr));
}

__device__ __forceinline__ void cp16(uint32_t smem_dst, const void* gmem_src) {
    asm volatile("cp.async.cg.shared.global [%0], [%1], 16;\n"
                 :: "r"(smem_dst), "l"(gmem_src));
}
__device__ __forceinline__ void cp_commit() {
    asm volatile("cp.async.commit_group;\n");
}
template <int N>
__device__ __forceinline__ void cp_wait() {
    asm volatile("cp.async.wait_group %0;\n" :: "n"(N));
}

__device__ __forceinline__ void split_bf(float x, __nv_bfloat16& h, __nv_bfloat16& l) {
    h = __float2bfloat16(x);
    l = __float2bfloat16(x - __bfloat162float(h));
}
__device__ __forceinline__ void split_h(float x, __half& h, __half& l) {
    h = __float2half_rn(x);
    l = __float2half_rn(x - __half2float(h));
}
__device__ __forceinline__ uint32_t pack2(__nv_bfloat16 a, __nv_bfloat16 b) {
    return (uint32_t)__bfloat16_as_ushort(a) | ((uint32_t)__bfloat16_as_ushort(b) << 16);
}
__device__ __forceinline__ uint32_t pack2h(__half a, __half b) {
    return (uint32_t)__half_as_ushort(a) | ((uint32_t)__half_as_ushort(b) << 16);
}
__device__ __forceinline__ float exp2a(float x) {
    float r;
    asm("ex2.approx.ftz.f32 %0, %1;" : "=f"(r) : "f"(x));
    return r;
}

// ---------------------------------------------------------------------------
// Pre-split kernels
// ---------------------------------------------------------------------------
__global__ void splitx_kernel(const float* __restrict__ src, int n)
{
    int i = (blockIdx.x * blockDim.x + threadIdx.x) * 4;
    if (i >= n) return;
    float4 v = *(const float4*)(src + i);
    __nv_bfloat16 h0, l0, h1, l1, h2, l2, h3, l3;
    split_bf(v.x, h0, l0); split_bf(v.y, h1, l1);
    split_bf(v.z, h2, l2); split_bf(v.w, h3, l3);
    *(uint32_t*)(g_xh + i)     = pack2(h0, h1);
    *(uint32_t*)(g_xh + i + 2) = pack2(h2, h3);
    *(uint32_t*)(g_xl + i)     = pack2(l0, l1);
    *(uint32_t*)(g_xl + i + 2) = pack2(l2, l3);
    __half p0, q0, p1, q1, p2, q2, p3, q3;
    split_h(v.x, p0, q0); split_h(v.y, p1, q1);
    split_h(v.z, p2, q2); split_h(v.w, p3, q3);
    *(uint32_t*)(g_x16h + i)     = pack2h(p0, p1);
    *(uint32_t*)(g_x16h + i + 2) = pack2h(p2, p3);
    *(uint32_t*)(g_x16l + i)     = pack2h(q0, q1);
    *(uint32_t*)(g_x16l + i + 2) = pack2h(q2, q3);
}

__global__ void split4_kernel(const float* __restrict__ W0, const float* __restrict__ W1,
                              const float* __restrict__ W2, const float* __restrict__ W3)
{
    const int z = blockIdx.y;
    const float* src = (z == 0) ? W0 : (z == 1) ? W1 : (z == 2) ? W2 : W3;
    const size_t nw = (size_t)DMODEL * DMODEL;
    __nv_bfloat16* hi = g_wh + z * nw;
    __nv_bfloat16* lo = g_wl + z * nw;
    int i = (blockIdx.x * blockDim.x + threadIdx.x) * 4;
    if (i >= (int)nw) return;
    float4 v = *(const float4*)(src + i);
    if (z < 2) {
        __nv_bfloat16 h0, l0, h1, l1, h2, l2, h3, l3;
        split_bf(v.x, h0, l0); split_bf(v.y, h1, l1);
        split_bf(v.z, h2, l2); split_bf(v.w, h3, l3);
        *(uint32_t*)(hi + i)     = pack2(h0, h1);
        *(uint32_t*)(hi + i + 2) = pack2(h2, h3);
        *(uint32_t*)(lo + i)     = pack2(l0, l1);
        *(uint32_t*)(lo + i + 2) = pack2(l2, l3);
    } else {
        __half h0, l0, h1, l1, h2, l2, h3, l3;
        split_h(v.x, h0, l0); split_h(v.y, h1, l1);
        split_h(v.z, h2, l2); split_h(v.w, h3, l3);
        *(uint32_t*)(hi + i)     = pack2h(h0, h1);
        *(uint32_t*)(hi + i + 2) = pack2h(h2, h3);
        *(uint32_t*)(lo + i)     = pack2h(l0, l1);
        *(uint32_t*)(lo + i + 2) = pack2h(l2, l3);
    }
}

// ---------------------------------------------------------------------------
// GEMM (128x128 CTA, 256 thr, 2 CTAs/SM, single-sync pipeline, ldmatrix).
// MODE 1 + PROD 3: Q/K projections (bf16x3), z = blockIdx.z in {0,1}.
// MODE 1 + PROD 2: V projection (fp16 x 2 products), fp16 epilogue.
// MODE 0 + PROD 2: out projection (fp16 x 2), f32 epilogue.
// ---------------------------------------------------------------------------
#define SWG     20
#define PLANEW  (128 * SWG)
#define GSMEM_W (2 * 4 * PLANEW)

template <int MODE, int PROD>
__global__ __launch_bounds__(256, 2)
void gemm_k(float* __restrict__ Cout)
{
    extern __shared__ uint32_t smw[];

    const void *Ahp, *Alp, *Bhp, *Blp;
    if (MODE == 1 && PROD == 3) {
        const size_t wo = (size_t)blockIdx.z * DMODEL * DMODEL;
        Ahp = g_xh;  Alp = g_xl;
        Bhp = g_wh + wo;  Blp = g_wl + wo;
    } else if (MODE == 1) {            // V projection
        Ahp = g_x16h;  Alp = g_x16l;
        Bhp = g_wh + 2u * DMODEL * DMODEL;  Blp = g_wl + 2u * DMODEL * DMODEL;
    } else {                            // out projection
        Ahp = g_ctxh;  Alp = g_ctxl;
        Bhp = g_wh + 3u * DMODEL * DMODEL;  Blp = g_wl + 3u * DMODEL * DMODEL;
    }

    const int tid  = threadIdx.x;
    const int lane = tid & 31;
    const int wid  = tid >> 5;
    const int wm   = wid >> 1;
    const int wn   = wid & 1;
    const int gID  = lane >> 2;
    const int tg   = lane & 3;

    const int l7   = lane & 7;
    const int l15  = lane & 15;
    const int lb8  = (lane >> 3) & 1;
    const int lb16 = (lane >> 4) & 1;

    const int brow = blockIdx.y * 128;
    const int bcol = blockIdx.x * 128;

    const int srow = tid >> 1;
    const int cb   = (tid & 1) * 2;

    const uint32_t smem0 = (uint32_t)__cvta_generic_to_shared(smw);

    auto stage = [&](int buf, int k0) {
        const uint32_t base = smem0 + (uint32_t)(buf * 4 * PLANEW) * 4u;
        const uint16_t* gsrc[4] = {
            (const uint16_t*)Ahp + (size_t)(brow + srow) * DMODEL + k0,
            (const uint16_t*)Alp + (size_t)(brow + srow) * DMODEL + k0,
            (const uint16_t*)Bhp + (size_t)(bcol + srow) * DMODEL + k0,
            (const uint16_t*)Blp + (size_t)(bcol + srow) * DMODEL + k0 };
        const int NP = (PROD == 3) ? 4 : 3;
#pragma unroll
        for (int p = 0; p < 4; p++) {
            if (p >= NP) break;
#pragma unroll
            for (int j = 0; j < 2; j++) {
                const int c = cb + j;
                cp16(base + (uint32_t)(p * PLANEW + srow * SWG + c * 4) * 4u,
                     gsrc[p] + c * 8);
            }
        }
        cp_commit();
    };

    float acc[2][8][4];
#pragma unroll
    for (int mt = 0; mt < 2; mt++)
#pragma unroll
        for (int nt = 0; nt < 8; nt++)
#pragma unroll
            for (int i = 0; i < 4; i++) acc[mt][nt][i] = 0.0f;

    stage(0, 0);

    for (int kt = 0; kt < DMODEL / 32; kt++) {
        cp_wait<0>();
        __syncthreads();

        if (kt + 1 < DMODEL / 32)
            stage((kt + 1) & 1, (kt + 1) * 32);

        const uint32_t bufw = (uint32_t)((kt & 1) * 4 * PLANEW) * 4u;
        const uint32_t Ah_b = smem0 + bufw;
        const uint32_t Al_b = Ah_b + PLANEW * 4u;
        const uint32_t Bh_b = Al_b + PLANEW * 4u;
        const uint32_t Bl_b = Bh_b + PLANEW * 4u;

#pragma unroll
        for (int ks = 0; ks < 2; ks++) {
            const int wb = ks * 8;

            uint32_t ah[2][4], al[2][4];
#pragma unroll
            for (int mt = 0; mt < 2; mt++) {
                const uint32_t aoff =
                    (uint32_t)((wm * 32 + mt * 16 + l15) * SWG + wb + 4 * lb16) * 4u;
                ldsm4(ah[mt], Ah_b + aoff);
                ldsm4(al[mt], Al_b + aoff);
            }

#pragma unroll
            for (int np = 0; np < 4; np++) {
                const uint32_t boff =
                    (uint32_t)((wn * 64 + np * 16 + l7 + lb16 * 8) * SWG + wb + 4 * lb8) * 4u;
                uint32_t bhf[4];
                ldsm4(bhf, Bh_b + boff);

                if (PROD == 3) {
                    uint32_t blf[4];
                    ldsm4(blf, Bl_b + boff);
#pragma unroll
                    for (int half = 0; half < 2; half++) {
                        const int nt = 2 * np + half;
#pragma unroll
                        for (int mt = 0; mt < 2; mt++)
                            mma_bf16(acc[mt][nt], ah[mt][0], ah[mt][1], ah[mt][2], ah[mt][3],
                                     bhf[2 * half], bhf[2 * half + 1]);
                    }
#pragma unroll
                    for (int half = 0; half < 2; half++) {
                        const int nt = 2 * np + half;
#pragma unroll
                        for (int mt = 0; mt < 2; mt++)
                            mma_bf16(acc[mt][nt], ah[mt][0], ah[mt][1], ah[mt][2], ah[mt][3],
                                     blf[2 * half], blf[2 * half + 1]);
                    }
#pragma unroll
                    for (int half = 0; half < 2; half++) {
                        const int nt = 2 * np + half;
#pragma unroll
                        for (int mt = 0; mt < 2; mt++)
                            mma_bf16(acc[mt][nt], al[mt][0], al[mt][1], al[mt][2], al[mt][3],
                                     bhf[2 * half], bhf[2 * half + 1]);
                    }
                } else {
#pragma unroll
                    for (int half = 0; half < 2; half++) {
                        const int nt = 2 * np + half;
#pragma unroll
                        for (int mt = 0; mt < 2; mt++)
                            mma_f16(acc[mt][nt], ah[mt][0], ah[mt][1], ah[mt][2], ah[mt][3],
                                    bhf[2 * half], bhf[2 * half + 1]);
                    }
#pragma unroll
                    for (int half = 0; half < 2; half++) {
                        const int nt = 2 * np + half;
#pragma unroll
                        for (int mt = 0; mt < 2; mt++)
                            mma_f16(acc[mt][nt], al[mt][0], al[mt][1], al[mt][2], al[mt][3],
                                    bhf[2 * half], bhf[2 * half + 1]);
                    }
                }
            }
        }
    }

    if (MODE == 1) {
        const int z = (PROD == 3) ? (int)blockIdx.z : 2;
        const size_t zo = (size_t)z * (BHEADS * SEQ * HDIM);
#pragma unroll
        for (int mt = 0; mt < 2; mt++) {
            const int rbase = brow + wm * 32 + mt * 16 + gID;
#pragma unroll
            for (int nt = 0; nt < 8; nt++) {
                const int col = bcol + wn * 64 + nt * 8 + tg * 2;
                const int h = col >> 6;
                const int e = col & 63;
#pragma unroll
                for (int half = 0; half < 2; half++) {
                    const int r = rbase + half * 8;
                    const int b = r >> 11;
                    const int s = r & (SEQ - 1);
                    const size_t o = zo + ((size_t)(b * NHEADS + h) * SEQ + s) * HDIM + e;
                    const float v0 = acc[mt][nt][half * 2 + 0];
                    const float v1 = acc[mt][nt][half * 2 + 1];
                    if (PROD == 2) {          // V: fp16 planes
                        __half h0, l0, h1, l1;
                        split_h(v0, h0, l0);
                        split_h(v1, h1, l1);
                        *(uint32_t*)(g_qkvh + o) = pack2h(h0, h1);
                        *(uint32_t*)(g_qkvl + o) = pack2h(l0, l1);
                    } else {                   // Q/K: bf16 planes
                        __nv_bfloat16 h0, l0, h1, l1;
                        split_bf(v0, h0, l0);
                        split_bf(v1, h1, l1);
                        *(uint32_t*)(g_qkvh + o) = pack2(h0, h1);
                        *(uint32_t*)(g_qkvl + o) = pack2(l0, l1);
                    }
                }
            }
        }
    } else {
#pragma unroll
        for (int mt = 0; mt < 2; mt++) {
            const int rbase = brow + wm * 32 + mt * 16 + gID;
#pragma unroll
            for (int nt = 0; nt < 8; nt++) {
                const int col = bcol + wn * 64 + nt * 8 + tg * 2;
#pragma unroll
                for (int half = 0; half < 2; half++) {
                    const int r = rbase + half * 8;
                    float2 v = make_float2(acc[mt][nt][half * 2], acc[mt][nt][half * 2 + 1]);
                    *(float2*)(Cout + (size_t)r * DMODEL + col) = v;
                }
            }
        }
    }
}

// ---------------------------------------------------------------------------
// Flash attention — R14-proven; epilogue writes ctx as fp16 hi/lo.
// ---------------------------------------------------------------------------
#define BQ   128
#define BKT  64
#define SWF  36
#define QW   (BQ * SWF)
#define KW   (BKT * SWF)
#define KVBUF_B (4u * KW * 4u)
#define FSMEM_W (2*QW + 8*KW)        // 110592 B

__global__ __launch_bounds__(256, 2)
void flash_bf()
{
    extern __shared__ uint32_t smw[];

    const int tid  = threadIdx.x;
    const int lane = tid & 31;
    const int wid  = tid >> 5;
    const int gID  = lane >> 2;
    const int tg   = lane & 3;

    const int bh    = blockIdx.y;
    const int b     = bh >> 4;
    const int h     = bh & 15;
    const int qi    = (int)gridDim.x - 1 - (int)blockIdx.x;
    const int qbase = qi * BQ;

    const __nv_bfloat16* Qhp = g_qkvh + (size_t)bh * (SEQ * HDIM);
    const __nv_bfloat16* Qlp = g_qkvl + (size_t)bh * (SEQ * HDIM);
    const __nv_bfloat16* Khp = g_qkvh + (size_t)(BHEADS + bh) * (SEQ * HDIM);
    const __nv_bfloat16* Klp = g_qkvl + (size_t)(BHEADS + bh) * (SEQ * HDIM);
    const __nv_bfloat16* Vhp = g_qkvh + (size_t)(2 * BHEADS + bh) * (SEQ * HDIM);  // fp16 bits
    const __nv_bfloat16* Vlp = g_qkvl + (size_t)(2 * BHEADS + bh) * (SEQ * HDIM);  // fp16 bits

    const uint32_t smem0 = (uint32_t)__cvta_generic_to_shared(smw);
    const uint32_t Qh_b = smem0;
    const uint32_t Ql_b = Qh_b + QW * 4u;
    const uint32_t KV0  = Ql_b + QW * 4u;

    {
        const int r  = tid >> 1;
        const int c0 = (tid & 1) * 4;
        const __nv_bfloat16* sh = Qhp + (size_t)(qbase + r) * HDIM;
        const __nv_bfloat16* sl = Qlp + (size_t)(qbase + r) * HDIM;
#pragma unroll
        for (int j = 0; j < 4; j++) {
            const int c = c0 + j;
            cp16(Qh_b + (uint32_t)(r * SWF + c * 4) * 4u, sh + c * 8);
            cp16(Ql_b + (uint32_t)(r * SWF + c * 4) * 4u, sl + c * 8);
        }
        cp_commit();
    }

    const int sr  = tid >> 2;
    const int sc0 = (tid & 3) * 2;

    auto stage_kv = [&](int buf, int kt) {
        const uint32_t bb = KV0 + (uint32_t)buf * KVBUF_B;
        const __nv_bfloat16* skh = Khp + (size_t)(kt * BKT + sr) * HDIM;
        const __nv_bfloat16* skl = Klp + (size_t)(kt * BKT + sr) * HDIM;
        const __nv_bfloat16* svh = Vhp + (size_t)(kt * BKT + sr) * HDIM;
        const __nv_bfloat16* svl = Vlp + (size_t)(kt * BKT + sr) * HDIM;
#pragma unroll
        for (int j = 0; j < 2; j++) {
            const int c = sc0 + j;
            const uint32_t so = (uint32_t)(sr * SWF + c * 4) * 4u;
            cp16(bb + so,                skh + c * 8);
            cp16(bb + KW * 4u + so,      skl + c * 8);
            cp16(bb + 2u * KW * 4u + so, svh + c * 8);
            cp16(bb + 3u * KW * 4u + so, svl + c * 8);
        }
        cp_commit();
    };

    const int l7  = lane & 7;
    const int l15 = lane & 15;
    const int lb8 = (lane >> 3) & 1;
    const int lb16 = (lane >> 4) & 1;

    const int rloc = wid * 16 + gID;

    float m0 = -1e30f, m1 = -1e30f, l0 = 0.0f, l1 = 0.0f;
    float oacc[8][4];
#pragma unroll
    for (int nt = 0; nt < 8; nt++)
#pragma unroll
        for (int i = 0; i < 4; i++) oacc[nt][i] = 0.0f;

    const int nkt = 2 * qi + 2;
    const float scale2 = 0.125f * 1.44269504f;

    stage_kv(0, 0);

    for (int kt = 0; kt < nkt; kt++) {
        cp_wait<0>();
        __syncthreads();

        if (kt + 1 < nkt)
            stage_kv((kt + 1) & 1, kt + 1);

        const uint32_t bb  = KV0 + (uint32_t)(kt & 1) * KVBUF_B;
        const uint32_t Kh_b = bb;
        const uint32_t Kl_b = bb + KW * 4u;
        const uint32_t Vh_b = bb + 2u * KW * 4u;
        const uint32_t Vl_b = bb + 3u * KW * 4u;

        float sacc[8][4];
#pragma unroll
        for (int nt = 0; nt < 8; nt++)
#pragma unroll
            for (int i = 0; i < 4; i++) sacc[nt][i] = 0.0f;

#pragma unroll
        for (int ks = 0; ks < 4; ks++) {
            uint32_t qh[4], ql[4];
            const uint32_t qoff = (uint32_t)((rloc - gID + l15) * SWF + 8 * ks + 4 * lb16) * 4u;
            ldsm4(qh, Qh_b + qoff);
            ldsm4(ql, Ql_b + qoff);
#pragma unroll
            for (int np = 0; np < 4; np++) {
                uint32_t kh[4], kl[4];
                const uint32_t koff =
                    (uint32_t)((np * 16 + l7 + lb16 * 8) * SWF + 8 * ks + 4 * lb8) * 4u;
                ldsm4(kh, Kh_b + koff);
                ldsm4(kl, Kl_b + koff);
                mma_bf16(sacc[2 * np],     qh[0], qh[1], qh[2], qh[3], kh[0], kh[1]);
                mma_bf16(sacc[2 * np + 1], qh[0], qh[1], qh[2], qh[3], kh[2], kh[3]);
                mma_bf16(sacc[2 * np],     qh[0], qh[1], qh[2], qh[3], kl[0], kl[1]);
                mma_bf16(sacc[2 * np + 1], qh[0], qh[1], qh[2], qh[3], kl[2], kl[3]);
                mma_bf16(sacc[2 * np],     ql[0], ql[1], ql[2], ql[3], kh[0], kh[1]);
                mma_bf16(sacc[2 * np + 1], ql[0], ql[1], ql[2], ql[3], kh[2], kh[3]);
            }
        }

        const bool diag = (kt >= 2 * qi);
        uint32_t pf[4][4];

#pragma unroll
        for (int half = 0; half < 2; half++) {
            const int rg = qbase + rloc + half * 8;
            float& m = half ? m1 : m0;
            float& l = half ? l1 : l0;

            float mx = -1e30f;
#pragma unroll
            for (int nt = 0; nt < 8; nt++) {
#pragma unroll
                for (int j = 0; j < 2; j++) {
                    float s = sacc[nt][half * 2 + j] * scale2;
                    if (diag) {
                        const int cg = kt * BKT + nt * 8 + tg * 2 + j;
                        if (cg > rg) s = -1e30f;
                    }
                    sacc[nt][half * 2 + j] = s;
                    mx = fmaxf(mx, s);
                }
            }
            mx = fmaxf(mx, __shfl_xor_sync(0xffffffffu, mx, 1));
            mx = fmaxf(mx, __shfl_xor_sync(0xffffffffu, mx, 2));

            const float mn = fmaxf(m, mx);
            const float alpha = exp2a(m - mn);
            float rs = 0.0f;
#pragma unroll
            for (int nt = 0; nt < 8; nt++) {
                float p0 = exp2a(sacc[nt][half * 2 + 0] - mn);
                float p1 = exp2a(sacc[nt][half * 2 + 1] - mn);
                rs += p0 + p1;
                const int ks   = nt >> 1;
                const int slot = (nt & 1) * 2 + half;
                pf[ks][slot] = pack2h(__float2half_rn(p0), __float2half_rn(p1));
            }
            rs += __shfl_xor_sync(0xffffffffu, rs, 1);
            rs += __shfl_xor_sync(0xffffffffu, rs, 2);
            l = l * alpha + rs;
            m = mn;
#pragma unroll
            for (int nt = 0; nt < 8; nt++) {
                oacc[nt][half * 2 + 0] *= alpha;
                oacc[nt][half * 2 + 1] *= alpha;
            }
        }

#pragma unroll
        for (int ks = 0; ks < 4; ks++) {
#pragma unroll
            for (int np = 0; np < 4; np++) {
                uint32_t vh[4], vl[4];
                const uint32_t voff =
                    (uint32_t)((ks * 16 + l7 + lb8 * 8) * SWF + 8 * np + 4 * lb16) * 4u;
                ldsm4t(vh, Vh_b + voff);
                ldsm4t(vl, Vl_b + voff);
                mma_f16(oacc[2 * np],     pf[ks][0], pf[ks][1], pf[ks][2], pf[ks][3], vh[0], vh[1]);
                mma_f16(oacc[2 * np + 1], pf[ks][0], pf[ks][1], pf[ks][2], pf[ks][3], vh[2], vh[3]);
                mma_f16(oacc[2 * np],     pf[ks][0], pf[ks][1], pf[ks][2], pf[ks][3], vl[0], vl[1]);
                mma_f16(oacc[2 * np + 1], pf[ks][0], pf[ks][1], pf[ks][2], pf[ks][3], vl[2], vl[3]);
            }
        }
    }

    // ---- Epilogue: ctx as fp16 hi/lo ----
    const float inv0 = 1.0f / l0;
    const float inv1 = 1.0f / l1;
#pragma unroll
    for (int half = 0; half < 2; half++) {
        const float inv = half ? inv1 : inv0;
        const int rg = qbase + rloc + half * 8;
        const size_t rowo = ((size_t)b * SEQ + rg) * DMODEL + h * HDIM;
#pragma unroll
        for (int nt = 0; nt < 8; nt++) {
            float v0 = oacc[nt][half * 2 + 0] * inv;
            float v1 = oacc[nt][half * 2 + 1] * inv;
            __half h0, lo0, h1, lo1;
            split_h(v0, h0, lo0);
            split_h(v1, h1, lo1);
            const size_t o = rowo + nt * 8 + tg * 2;
            *(uint32_t*)(g_ctxh + o) = pack2h(h0, h1);
            *(uint32_t*)(g_ctxl + o) = pack2h(lo0, lo1);
        }
    }
}

// ---------------------------------------------------------------------------
extern "C" void kernel_launch(void* const* d_in, const int* in_sizes, int n_in,
                              void* d_out, int out_size)
{
    const float* x  = (const float*)d_in[0];
    const float* Wq = (const float*)d_in[1];
    const float* Wk = (const float*)d_in[2];
    const float* Wv = (const float*)d_in[3];
    const float* Wo = (const float*)d_in[4];
    float* out = (float*)d_out;

    const int gsmem = GSMEM_W * 4;     // 81920 B
    const int fsmem = FSMEM_W * 4;     // 110592 B

    cudaFuncSetAttribute(gemm_k<1, 3>,
                         cudaFuncAttributeMaxDynamicSharedMemorySize, gsmem);
    cudaFuncSetAttribute(gemm_k<1, 2>,
                         cudaFuncAttributeMaxDynamicSharedMemorySize, gsmem);
    cudaFuncSetAttribute(gemm_k<0, 2>,
                         cudaFuncAttributeMaxDynamicSharedMemorySize, gsmem);
    cudaFuncSetAttribute(flash_bf,
                         cudaFuncAttributeMaxDynamicSharedMemorySize, fsmem);

    const int nx = ROWS * DMODEL;
    const int nw = DMODEL * DMODEL;
    splitx_kernel<<<(nx / 4 + 255) / 256, 256>>>(x, nx);
    dim3 gs((nw / 4 + 255) / 256, 4);
    split4_kernel<<<gs, 256>>>(Wq, Wk, Wv, Wo);

    // 1a) Q/K projections (bf16x3)
    dim3 g1(DMODEL / 128, ROWS / 128, 2);
    gemm_k<1, 3><<<g1, 256, gsmem>>>(nullptr);
    // 1b) V projection (fp16 x 2)
    dim3 g1v(DMODEL / 128, ROWS / 128, 1);
    gemm_k<1, 2><<<g1v, 256, gsmem>>>(nullptr);

    // 2) Causal flash attention
    dim3 g2(SEQ / BQ, BHEADS);
    flash_bf<<<g2, 256, fsmem>>>();

    // 3) Output projection (fp16 x 2)
    dim3 g3(DMODEL / 128, ROWS / 128, 1);
    gemm_k<0, 2><<<g3, 256, gsmem>>>(out);
}

// round 17
// speedup vs baseline: 1.4541x; 1.0116x over previous
#include <cuda_runtime.h>
#include <cuda_bf16.h>
#include <cuda_fp16.h>
#include <cstdint>

#define BATCH   4
#define SEQ     2048
#define DMODEL  1024
#define NHEADS  16
#define HDIM    64
#define BHEADS  (BATCH * NHEADS)        // 64
#define ROWS    (BATCH * SEQ)           // 8192

// ---------------------------------------------------------------------------
// Device-global scratch.
// ---------------------------------------------------------------------------
__device__ __nv_bfloat16 g_xh[(size_t)ROWS * DMODEL];
__device__ __nv_bfloat16 g_xl[(size_t)ROWS * DMODEL];
__device__ __half        g_x16h[(size_t)ROWS * DMODEL];
__device__ __half        g_x16l[(size_t)ROWS * DMODEL];
__device__ __nv_bfloat16 g_wh[4u * DMODEL * DMODEL];
__device__ __nv_bfloat16 g_wl[4u * DMODEL * DMODEL];
__device__ __nv_bfloat16 g_qkvh[3u * BHEADS * SEQ * HDIM];
__device__ __nv_bfloat16 g_qkvl[3u * BHEADS * SEQ * HDIM];
__device__ __nv_bfloat16 g_ctxh[(size_t)ROWS * DMODEL];   // fp16 bits
__device__ __nv_bfloat16 g_ctxl[(size_t)ROWS * DMODEL];   // fp16 bits

// ---------------------------------------------------------------------------
// Helpers
// ---------------------------------------------------------------------------
__device__ __forceinline__ void mma_bf16(float* c,
                                         uint32_t a0, uint32_t a1, uint32_t a2, uint32_t a3,
                                         uint32_t b0, uint32_t b1) {
    asm volatile(
        "mma.sync.aligned.m16n8k16.row.col.f32.bf16.bf16.f32 "
        "{%0,%1,%2,%3}, {%4,%5,%6,%7}, {%8,%9}, {%0,%1,%2,%3};\n"
        : "+f"(c[0]), "+f"(c[1]), "+f"(c[2]), "+f"(c[3])
        : "r"(a0), "r"(a1), "r"(a2), "r"(a3), "r"(b0), "r"(b1));
}
__device__ __forceinline__ void mma_f16(float* c,
                                        uint32_t a0, uint32_t a1, uint32_t a2, uint32_t a3,
                                        uint32_t b0, uint32_t b1) {
    asm volatile(
        "mma.sync.aligned.m16n8k16.row.col.f32.f16.f16.f32 "
        "{%0,%1,%2,%3}, {%4,%5,%6,%7}, {%8,%9}, {%0,%1,%2,%3};\n"
        : "+f"(c[0]), "+f"(c[1]), "+f"(c[2]), "+f"(c[3])
        : "r"(a0), "r"(a1), "r"(a2), "r"(a3), "r"(b0), "r"(b1));
}

__device__ __forceinline__ void ldsm4(uint32_t* r, uint32_t addr) {
    asm volatile("ldmatrix.sync.aligned.m8n8.x4.shared.b16 {%0,%1,%2,%3}, [%4];"
                 : "=r"(r[0]), "=r"(r[1]), "=r"(r[2]), "=r"(r[3]) : "r"(addr));
}
__device__ __forceinline__ void ldsm4t(uint32_t* r, uint32_t addr) {
    asm volatile("ldmatrix.sync.aligned.m8n8.x4.trans.shared.b16 {%0,%1,%2,%3}, [%4];"
                 : "=r"(r[0]), "=r"(r[1]), "=r"(r[2]), "=r"(r[3]) : "r"(addr));
}

__device__ __forceinline__ void cp16(uint32_t smem_dst, const void* gmem_src) {
    asm volatile("cp.async.cg.shared.global [%0], [%1], 16;\n"
                 :: "r"(smem_dst), "l"(gmem_src));
}
__device__ __forceinline__ void cp_commit() {
    asm volatile("cp.async.commit_group;\n");
}
template <int N>
__device__ __forceinline__ void cp_wait() {
    asm volatile("cp.async.wait_group %0;\n" :: "n"(N));
}

__device__ __forceinline__ void split_bf(float x, __nv_bfloat16& h, __nv_bfloat16& l) {
    h = __float2bfloat16(x);
    l = __float2bfloat16(x - __bfloat162float(h));
}
__device__ __forceinline__ void split_h(float x, __half& h, __half& l) {
    h = __float2half_rn(x);
    l = __float2half_rn(x - __half2float(h));
}
__device__ __forceinline__ uint32_t pack2(__nv_bfloat16 a, __nv_bfloat16 b) {
    return (uint32_t)__bfloat16_as_ushort(a) | ((uint32_t)__bfloat16_as_ushort(b) << 16);
}
__device__ __forceinline__ uint32_t pack2h(__half a, __half b) {
    return (uint32_t)__half_as_ushort(a) | ((uint32_t)__half_as_ushort(b) << 16);
}
__device__ __forceinline__ float exp2a(float x) {
    float r;
    asm("ex2.approx.ftz.f32 %0, %1;" : "=f"(r) : "f"(x));
    return r;
}

// ---------------------------------------------------------------------------
// Fused pre-split kernel: y 0..3 -> weights, y 4.. -> x
// ---------------------------------------------------------------------------
__global__ void split_all(const float* __restrict__ x,
                          const float* __restrict__ W0, const float* __restrict__ W1,
                          const float* __restrict__ W2, const float* __restrict__ W3)
{
    const int y = blockIdx.y;
    if (y < 4) {
        const float* src = (y == 0) ? W0 : (y == 1) ? W1 : (y == 2) ? W2 : W3;
        const size_t nw = (size_t)DMODEL * DMODEL;
        __nv_bfloat16* hi = g_wh + y * nw;
        __nv_bfloat16* lo = g_wl + y * nw;
        int i = (blockIdx.x * blockDim.x + threadIdx.x) * 4;
        if (i >= (int)nw) return;
        float4 v = *(const float4*)(src + i);
        if (y < 2) {
            __nv_bfloat16 h0, l0, h1, l1, h2, l2, h3, l3;
            split_bf(v.x, h0, l0); split_bf(v.y, h1, l1);
            split_bf(v.z, h2, l2); split_bf(v.w, h3, l3);
            *(uint32_t*)(hi + i)     = pack2(h0, h1);
            *(uint32_t*)(hi + i + 2) = pack2(h2, h3);
            *(uint32_t*)(lo + i)     = pack2(l0, l1);
            *(uint32_t*)(lo + i + 2) = pack2(l2, l3);
        } else {
            __half h0, l0, h1, l1, h2, l2, h3, l3;
            split_h(v.x, h0, l0); split_h(v.y, h1, l1);
            split_h(v.z, h2, l2); split_h(v.w, h3, l3);
            *(uint32_t*)(hi + i)     = pack2h(h0, h1);
            *(uint32_t*)(hi + i + 2) = pack2h(h2, h3);
            *(uint32_t*)(lo + i)     = pack2h(l0, l1);
            *(uint32_t*)(lo + i + 2) = pack2h(l2, l3);
        }
    } else {
        const int n = ROWS * DMODEL;
        int i = ((y - 4) * gridDim.x * blockDim.x + blockIdx.x * blockDim.x + threadIdx.x) * 4;
        if (i >= n) return;
        float4 v = *(const float4*)(x + i);
        __nv_bfloat16 h0, l0, h1, l1, h2, l2, h3, l3;
        split_bf(v.x, h0, l0); split_bf(v.y, h1, l1);
        split_bf(v.z, h2, l2); split_bf(v.w, h3, l3);
        *(uint32_t*)(g_xh + i)     = pack2(h0, h1);
        *(uint32_t*)(g_xh + i + 2) = pack2(h2, h3);
        *(uint32_t*)(g_xl + i)     = pack2(l0, l1);
        *(uint32_t*)(g_xl + i + 2) = pack2(l2, l3);
        __half p0, q0, p1, q1, p2, q2, p3, q3;
        split_h(v.x, p0, q0); split_h(v.y, p1, q1);
        split_h(v.z, p2, q2); split_h(v.w, p3, q3);
        *(uint32_t*)(g_x16h + i)     = pack2h(p0, p1);
        *(uint32_t*)(g_x16h + i + 2) = pack2h(p2, p3);
        *(uint32_t*)(g_x16l + i)     = pack2h(q0, q1);
        *(uint32_t*)(g_x16l + i + 2) = pack2h(q2, q3);
    }
}

// ---------------------------------------------------------------------------
// GEMM core (inlined device fn). 128x128 CTA, 256 thr, 2 CTAs/SM,
// single-sync pipeline, ldmatrix fragments.
// MODE 1 + PROD 3: Q/K projections (bf16x3), z in {0,1}.
// MODE 1 + PROD 2: V projection (fp16 x 2), fp16 epilogue (z == 2).
// MODE 0 + PROD 2: out projection (fp16 x 2), f32 epilogue.
// ---------------------------------------------------------------------------
#define SWG     20
#define PLANEW  (128 * SWG)
#define GSMEM_W (2 * 4 * PLANEW)

template <int MODE, int PROD>
__device__ __forceinline__ void gemm_core(uint32_t* smw, int z, float* Cout)
{
    const void *Ahp, *Alp, *Bhp, *Blp;
    if (MODE == 1 && PROD == 3) {
        const size_t wo = (size_t)z * DMODEL * DMODEL;
        Ahp = g_xh;  Alp = g_xl;
        Bhp = g_wh + wo;  Blp = g_wl + wo;
    } else if (MODE == 1) {            // V projection
        Ahp = g_x16h;  Alp = g_x16l;
        Bhp = g_wh + 2u * DMODEL * DMODEL;  Blp = g_wl + 2u * DMODEL * DMODEL;
    } else {                            // out projection
        Ahp = g_ctxh;  Alp = g_ctxl;
        Bhp = g_wh + 3u * DMODEL * DMODEL;  Blp = g_wl + 3u * DMODEL * DMODEL;
    }

    const int tid  = threadIdx.x;
    const int lane = tid & 31;
    const int wid  = tid >> 5;
    const int wm   = wid >> 1;
    const int wn   = wid & 1;
    const int gID  = lane >> 2;
    const int tg   = lane & 3;

    const int l7   = lane & 7;
    const int l15  = lane & 15;
    const int lb8  = (lane >> 3) & 1;
    const int lb16 = (lane >> 4) & 1;

    const int brow = blockIdx.y * 128;
    const int bcol = blockIdx.x * 128;

    const int srow = tid >> 1;
    const int cb   = (tid & 1) * 2;

    const uint32_t smem0 = (uint32_t)__cvta_generic_to_shared(smw);

    auto stage = [&](int buf, int k0) {
        const uint32_t base = smem0 + (uint32_t)(buf * 4 * PLANEW) * 4u;
        const uint16_t* gsrc[4] = {
            (const uint16_t*)Ahp + (size_t)(brow + srow) * DMODEL + k0,
            (const uint16_t*)Alp + (size_t)(brow + srow) * DMODEL + k0,
            (const uint16_t*)Bhp + (size_t)(bcol + srow) * DMODEL + k0,
            (const uint16_t*)Blp + (size_t)(bcol + srow) * DMODEL + k0 };
        const int NP = (PROD == 3) ? 4 : 3;
#pragma unroll
        for (int p = 0; p < 4; p++) {
            if (p >= NP) break;
#pragma unroll
            for (int j = 0; j < 2; j++) {
                const int c = cb + j;
                cp16(base + (uint32_t)(p * PLANEW + srow * SWG + c * 4) * 4u,
                     gsrc[p] + c * 8);
            }
        }
        cp_commit();
    };

    float acc[2][8][4];
#pragma unroll
    for (int mt = 0; mt < 2; mt++)
#pragma unroll
        for (int nt = 0; nt < 8; nt++)
#pragma unroll
            for (int i = 0; i < 4; i++) acc[mt][nt][i] = 0.0f;

    stage(0, 0);

    for (int kt = 0; kt < DMODEL / 32; kt++) {
        cp_wait<0>();
        __syncthreads();

        if (kt + 1 < DMODEL / 32)
            stage((kt + 1) & 1, (kt + 1) * 32);

        const uint32_t bufw = (uint32_t)((kt & 1) * 4 * PLANEW) * 4u;
        const uint32_t Ah_b = smem0 + bufw;
        const uint32_t Al_b = Ah_b + PLANEW * 4u;
        const uint32_t Bh_b = Al_b + PLANEW * 4u;
        const uint32_t Bl_b = Bh_b + PLANEW * 4u;

#pragma unroll
        for (int ks = 0; ks < 2; ks++) {
            const int wb = ks * 8;

            uint32_t ah[2][4], al[2][4];
#pragma unroll
            for (int mt = 0; mt < 2; mt++) {
                const uint32_t aoff =
                    (uint32_t)((wm * 32 + mt * 16 + l15) * SWG + wb + 4 * lb16) * 4u;
                ldsm4(ah[mt], Ah_b + aoff);
                ldsm4(al[mt], Al_b + aoff);
            }

#pragma unroll
            for (int np = 0; np < 4; np++) {
                const uint32_t boff =
                    (uint32_t)((wn * 64 + np * 16 + l7 + lb16 * 8) * SWG + wb + 4 * lb8) * 4u;
                uint32_t bhf[4];
                ldsm4(bhf, Bh_b + boff);

                if (PROD == 3) {
                    uint32_t blf[4];
                    ldsm4(blf, Bl_b + boff);
#pragma unroll
                    for (int half = 0; half < 2; half++) {
                        const int nt = 2 * np + half;
#pragma unroll
                        for (int mt = 0; mt < 2; mt++)
                            mma_bf16(acc[mt][nt], ah[mt][0], ah[mt][1], ah[mt][2], ah[mt][3],
                                     bhf[2 * half], bhf[2 * half + 1]);
                    }
#pragma unroll
                    for (int half = 0; half < 2; half++) {
                        const int nt = 2 * np + half;
#pragma unroll
                        for (int mt = 0; mt < 2; mt++)
                            mma_bf16(acc[mt][nt], ah[mt][0], ah[mt][1], ah[mt][2], ah[mt][3],
                                     blf[2 * half], blf[2 * half + 1]);
                    }
#pragma unroll
                    for (int half = 0; half < 2; half++) {
                        const int nt = 2 * np + half;
#pragma unroll
                        for (int mt = 0; mt < 2; mt++)
                            mma_bf16(acc[mt][nt], al[mt][0], al[mt][1], al[mt][2], al[mt][3],
                                     bhf[2 * half], bhf[2 * half + 1]);
                    }
                } else {
#pragma unroll
                    for (int half = 0; half < 2; half++) {
                        const int nt = 2 * np + half;
#pragma unroll
                        for (int mt = 0; mt < 2; mt++)
                            mma_f16(acc[mt][nt], ah[mt][0], ah[mt][1], ah[mt][2], ah[mt][3],
                                    bhf[2 * half], bhf[2 * half + 1]);
                    }
#pragma unroll
                    for (int half = 0; half < 2; half++) {
                        const int nt = 2 * np + half;
#pragma unroll
                        for (int mt = 0; mt < 2; mt++)
                            mma_f16(acc[mt][nt], al[mt][0], al[mt][1], al[mt][2], al[mt][3],
                                    bhf[2 * half], bhf[2 * half + 1]);
                    }
                }
            }
        }
    }

    if (MODE == 1) {
        const size_t zo = (size_t)z * (BHEADS * SEQ * HDIM);
#pragma unroll
        for (int mt = 0; mt < 2; mt++) {
            const int rbase = brow + wm * 32 + mt * 16 + gID;
#pragma unroll
            for (int nt = 0; nt < 8; nt++) {
                const int col = bcol + wn * 64 + nt * 8 + tg * 2;
                const int h = col >> 6;
                const int e = col & 63;
#pragma unroll
                for (int half = 0; half < 2; half++) {
                    const int r = rbase + half * 8;
                    const int b = r >> 11;
                    const int s = r & (SEQ - 1);
                    const size_t o = zo + ((size_t)(b * NHEADS + h) * SEQ + s) * HDIM + e;
                    const float v0 = acc[mt][nt][half * 2 + 0];
                    const float v1 = acc[mt][nt][half * 2 + 1];
                    if (PROD == 2) {          // V: fp16 planes
                        __half h0, l0, h1, l1;
                        split_h(v0, h0, l0);
                        split_h(v1, h1, l1);
                        *(uint32_t*)(g_qkvh + o) = pack2h(h0, h1);
                        *(uint32_t*)(g_qkvl + o) = pack2h(l0, l1);
                    } else {                   // Q/K: bf16 planes
                        __nv_bfloat16 h0, l0, h1, l1;
                        split_bf(v0, h0, l0);
                        split_bf(v1, h1, l1);
                        *(uint32_t*)(g_qkvh + o) = pack2(h0, h1);
                        *(uint32_t*)(g_qkvl + o) = pack2(l0, l1);
                    }
                }
            }
        }
    } else {
#pragma unroll
        for (int mt = 0; mt < 2; mt++) {
            const int rbase = brow + wm * 32 + mt * 16 + gID;
#pragma unroll
            for (int nt = 0; nt < 8; nt++) {
                const int col = bcol + wn * 64 + nt * 8 + tg * 2;
#pragma unroll
                for (int half = 0; half < 2; half++) {
                    const int r = rbase + half * 8;
                    float2 v = make_float2(acc[mt][nt][half * 2], acc[mt][nt][half * 2 + 1]);
                    *(float2*)(Cout + (size_t)r * DMODEL + col) = v;
                }
            }
        }
    }
}

// Fused QKV projection: one launch, z = 0,1 (bf16x3) / 2 (fp16x2)
__global__ __launch_bounds__(256, 2)
void gemm_qkv()
{
    extern __shared__ uint32_t smw[];
    const int z = blockIdx.z;
    if (z == 2)
        gemm_core<1, 2>(smw, 2, nullptr);
    else
        gemm_core<1, 3>(smw, z, nullptr);
}

// Out projection
__global__ __launch_bounds__(256, 2)
void gemm_out(float* __restrict__ Cout)
{
    extern __shared__ uint32_t smw[];
    gemm_core<0, 2>(smw, 3, Cout);
}

// ---------------------------------------------------------------------------
// Flash attention — R16-proven (QK bf16x3, PV fp16x2, exp2 softmax,
// double-buffered K/V, single-sync pipeline). ctx written as fp16 hi/lo.
// ---------------------------------------------------------------------------
#define BQ   128
#define BKT  64
#define SWF  36
#define QW   (BQ * SWF)
#define KW   (BKT * SWF)
#define KVBUF_B (4u * KW * 4u)
#define FSMEM_W (2*QW + 8*KW)        // 110592 B

__global__ __launch_bounds__(256, 2)
void flash_bf()
{
    extern __shared__ uint32_t smw[];

    const int tid  = threadIdx.x;
    const int lane = tid & 31;
    const int wid  = tid >> 5;
    const int gID  = lane >> 2;
    const int tg   = lane & 3;

    const int bh    = blockIdx.y;
    const int b     = bh >> 4;
    const int h     = bh & 15;
    const int qi    = (int)gridDim.x - 1 - (int)blockIdx.x;
    const int qbase = qi * BQ;

    const __nv_bfloat16* Qhp = g_qkvh + (size_t)bh * (SEQ * HDIM);
    const __nv_bfloat16* Qlp = g_qkvl + (size_t)bh * (SEQ * HDIM);
    const __nv_bfloat16* Khp = g_qkvh + (size_t)(BHEADS + bh) * (SEQ * HDIM);
    const __nv_bfloat16* Klp = g_qkvl + (size_t)(BHEADS + bh) * (SEQ * HDIM);
    const __nv_bfloat16* Vhp = g_qkvh + (size_t)(2 * BHEADS + bh) * (SEQ * HDIM);  // fp16 bits
    const __nv_bfloat16* Vlp = g_qkvl + (size_t)(2 * BHEADS + bh) * (SEQ * HDIM);  // fp16 bits

    const uint32_t smem0 = (uint32_t)__cvta_generic_to_shared(smw);
    const uint32_t Qh_b = smem0;
    const uint32_t Ql_b = Qh_b + QW * 4u;
    const uint32_t KV0  = Ql_b + QW * 4u;

    {
        const int r  = tid >> 1;
        const int c0 = (tid & 1) * 4;
        const __nv_bfloat16* sh = Qhp + (size_t)(qbase + r) * HDIM;
        const __nv_bfloat16* sl = Qlp + (size_t)(qbase + r) * HDIM;
#pragma unroll
        for (int j = 0; j < 4; j++) {
            const int c = c0 + j;
            cp16(Qh_b + (uint32_t)(r * SWF + c * 4) * 4u, sh + c * 8);
            cp16(Ql_b + (uint32_t)(r * SWF + c * 4) * 4u, sl + c * 8);
        }
        cp_commit();
    }

    const int sr  = tid >> 2;
    const int sc0 = (tid & 3) * 2;

    auto stage_kv = [&](int buf, int kt) {
        const uint32_t bb = KV0 + (uint32_t)buf * KVBUF_B;
        const __nv_bfloat16* skh = Khp + (size_t)(kt * BKT + sr) * HDIM;
        const __nv_bfloat16* skl = Klp + (size_t)(kt * BKT + sr) * HDIM;
        const __nv_bfloat16* svh = Vhp + (size_t)(kt * BKT + sr) * HDIM;
        const __nv_bfloat16* svl = Vlp + (size_t)(kt * BKT + sr) * HDIM;
#pragma unroll
        for (int j = 0; j < 2; j++) {
            const int c = sc0 + j;
            const uint32_t so = (uint32_t)(sr * SWF + c * 4) * 4u;
            cp16(bb + so,                skh + c * 8);
            cp16(bb + KW * 4u + so,      skl + c * 8);
            cp16(bb + 2u * KW * 4u + so, svh + c * 8);
            cp16(bb + 3u * KW * 4u + so, svl + c * 8);
        }
        cp_commit();
    };

    const int l7  = lane & 7;
    const int l15 = lane & 15;
    const int lb8 = (lane >> 3) & 1;
    const int lb16 = (lane >> 4) & 1;

    const int rloc = wid * 16 + gID;

    float m0 = -1e30f, m1 = -1e30f, l0 = 0.0f, l1 = 0.0f;
    float oacc[8][4];
#pragma unroll
    for (int nt = 0; nt < 8; nt++)
#pragma unroll
        for (int i = 0; i < 4; i++) oacc[nt][i] = 0.0f;

    const int nkt = 2 * qi + 2;
    const float scale2 = 0.125f * 1.44269504f;

    stage_kv(0, 0);

    for (int kt = 0; kt < nkt; kt++) {
        cp_wait<0>();
        __syncthreads();

        if (kt + 1 < nkt)
            stage_kv((kt + 1) & 1, kt + 1);

        const uint32_t bb  = KV0 + (uint32_t)(kt & 1) * KVBUF_B;
        const uint32_t Kh_b = bb;
        const uint32_t Kl_b = bb + KW * 4u;
        const uint32_t Vh_b = bb + 2u * KW * 4u;
        const uint32_t Vl_b = bb + 3u * KW * 4u;

        float sacc[8][4];
#pragma unroll
        for (int nt = 0; nt < 8; nt++)
#pragma unroll
            for (int i = 0; i < 4; i++) sacc[nt][i] = 0.0f;

#pragma unroll
        for (int ks = 0; ks < 4; ks++) {
            uint32_t qh[4], ql[4];
            const uint32_t qoff = (uint32_t)((rloc - gID + l15) * SWF + 8 * ks + 4 * lb16) * 4u;
            ldsm4(qh, Qh_b + qoff);
            ldsm4(ql, Ql_b + qoff);
#pragma unroll
            for (int np = 0; np < 4; np++) {
                uint32_t kh[4], kl[4];
                const uint32_t koff =
                    (uint32_t)((np * 16 + l7 + lb16 * 8) * SWF + 8 * ks + 4 * lb8) * 4u;
                ldsm4(kh, Kh_b + koff);
                ldsm4(kl, Kl_b + koff);
                mma_bf16(sacc[2 * np],     qh[0], qh[1], qh[2], qh[3], kh[0], kh[1]);
                mma_bf16(sacc[2 * np + 1], qh[0], qh[1], qh[2], qh[3], kh[2], kh[3]);
                mma_bf16(sacc[2 * np],     qh[0], qh[1], qh[2], qh[3], kl[0], kl[1]);
                mma_bf16(sacc[2 * np + 1], qh[0], qh[1], qh[2], qh[3], kl[2], kl[3]);
                mma_bf16(sacc[2 * np],     ql[0], ql[1], ql[2], ql[3], kh[0], kh[1]);
                mma_bf16(sacc[2 * np + 1], ql[0], ql[1], ql[2], ql[3], kh[2], kh[3]);
            }
        }

        const bool diag = (kt >= 2 * qi);
        uint32_t pf[4][4];

#pragma unroll
        for (int half = 0; half < 2; half++) {
            const int rg = qbase + rloc + half * 8;
            float& m = half ? m1 : m0;
            float& l = half ? l1 : l0;

            float mx = -1e30f;
#pragma unroll
            for (int nt = 0; nt < 8; nt++) {
#pragma unroll
                for (int j = 0; j < 2; j++) {
                    float s = sacc[nt][half * 2 + j] * scale2;
                    if (diag) {
                        const int cg = kt * BKT + nt * 8 + tg * 2 + j;
                        if (cg > rg) s = -1e30f;
                    }
                    sacc[nt][half * 2 + j] = s;
                    mx = fmaxf(mx, s);
                }
            }
            mx = fmaxf(mx, __shfl_xor_sync(0xffffffffu, mx, 1));
            mx = fmaxf(mx, __shfl_xor_sync(0xffffffffu, mx, 2));

            const float mn = fmaxf(m, mx);
            const float alpha = exp2a(m - mn);
            float rs = 0.0f;
#pragma unroll
            for (int nt = 0; nt < 8; nt++) {
                float p0 = exp2a(sacc[nt][half * 2 + 0] - mn);
                float p1 = exp2a(sacc[nt][half * 2 + 1] - mn);
                rs += p0 + p1;
                const int ks   = nt >> 1;
                const int slot = (nt & 1) * 2 + half;
                pf[ks][slot] = pack2h(__float2half_rn(p0), __float2half_rn(p1));
            }
            rs += __shfl_xor_sync(0xffffffffu, rs, 1);
            rs += __shfl_xor_sync(0xffffffffu, rs, 2);
            l = l * alpha + rs;
            m = mn;
#pragma unroll
            for (int nt = 0; nt < 8; nt++) {
                oacc[nt][half * 2 + 0] *= alpha;
                oacc[nt][half * 2 + 1] *= alpha;
            }
        }

#pragma unroll
        for (int ks = 0; ks < 4; ks++) {
#pragma unroll
            for (int np = 0; np < 4; np++) {
                uint32_t vh[4], vl[4];
                const uint32_t voff =
                    (uint32_t)((ks * 16 + l7 + lb8 * 8) * SWF + 8 * np + 4 * lb16) * 4u;
                ldsm4t(vh, Vh_b + voff);
                ldsm4t(vl, Vl_b + voff);
                mma_f16(oacc[2 * np],     pf[ks][0], pf[ks][1], pf[ks][2], pf[ks][3], vh[0], vh[1]);
                mma_f16(oacc[2 * np + 1], pf[ks][0], pf[ks][1], pf[ks][2], pf[ks][3], vh[2], vh[3]);
                mma_f16(oacc[2 * np],     pf[ks][0], pf[ks][1], pf[ks][2], pf[ks][3], vl[0], vl[1]);
                mma_f16(oacc[2 * np + 1], pf[ks][0], pf[ks][1], pf[ks][2], pf[ks][3], vl[2], vl[3]);
            }
        }
    }

    const float inv0 = 1.0f / l0;
    const float inv1 = 1.0f / l1;
#pragma unroll
    for (int half = 0; half < 2; half++) {
        const float inv = half ? inv1 : inv0;
        const int rg = qbase + rloc + half * 8;
        const size_t rowo = ((size_t)b * SEQ + rg) * DMODEL + h * HDIM;
#pragma unroll
        for (int nt = 0; nt < 8; nt++) {
            float v0 = oacc[nt][half * 2 + 0] * inv;
            float v1 = oacc[nt][half * 2 + 1] * inv;
            __half h0, lo0, h1, lo1;
            split_h(v0, h0, lo0);
            split_h(v1, h1, lo1);
            const size_t o = rowo + nt * 8 + tg * 2;
            *(uint32_t*)(g_ctxh + o) = pack2h(h0, h1);
            *(uint32_t*)(g_ctxl + o) = pack2h(lo0, lo1);
        }
    }
}

// ---------------------------------------------------------------------------
extern "C" void kernel_launch(void* const* d_in, const int* in_sizes, int n_in,
                              void* d_out, int out_size)
{
    const float* x  = (const float*)d_in[0];
    const float* Wq = (const float*)d_in[1];
    const float* Wk = (const float*)d_in[2];
    const float* Wv = (const float*)d_in[3];
    const float* Wo = (const float*)d_in[4];
    float* out = (float*)d_out;

    const int gsmem = GSMEM_W * 4;     // 81920 B
    const int fsmem = FSMEM_W * 4;     // 110592 B

    cudaFuncSetAttribute(gemm_qkv,
                         cudaFuncAttributeMaxDynamicSharedMemorySize, gsmem);
    cudaFuncSetAttribute(gemm_out,
                         cudaFuncAttributeMaxDynamicSharedMemorySize, gsmem);
    cudaFuncSetAttribute(flash_bf,
                         cudaFuncAttributeMaxDynamicSharedMemorySize, fsmem);

    // 0) fused pre-split: y 0..3 weights, y 4..11 x (8 slices of 1024 blocks)
    {
        const int nw_blocks = (DMODEL * DMODEL / 4) / 256;   // 1024
        dim3 gs(nw_blocks, 12);
        split_all<<<gs, 256>>>(x, Wq, Wk, Wv, Wo);
    }

    // 1) Fused QKV projections (z = 0,1 bf16x3; z = 2 fp16x2)
    dim3 g1(DMODEL / 128, ROWS / 128, 3);
    gemm_qkv<<<g1, 256, gsmem>>>();

    // 2) Causal flash attention
    dim3 g2(SEQ / BQ, BHEADS);
    flash_bf<<<g2, 256, fsmem>>>();

    // 3) Output projection (fp16 x 2)
    dim3 g3(DMODEL / 128, ROWS / 128, 1);
    gemm_out<<<g3, 256, gsmem>>>(out);
}